// round 9
// baseline (speedup 1.0000x reference)
#include <cuda_runtime.h>
#include <cuda_bf16.h>
#include <cstdint>

#define NB 4
#define NT 3072
#define ND 1024
#define NH 16
#define HD 64
#define TK 1025   // pooled K/V length: 1 + 3072/3

// GEMM tiling: 128x128 CTA tile, BK=32 halfs, 16 warps (4M x 4N), warp tile 32x32
#define BM 128
#define BN 128
#define BKH 32
#define TSTRIDE 40
#define TILE_HALFS (128 * TSTRIDE)
#define STAGE_HALFS (4 * TILE_HALFS)
#define NSTAGE 3
#define GEMM_SMEM (NSTAGE * STAGE_HALFS * 2)   // 122880 B, 1 CTA/SM
#define GTHREADS 512

// Flash tiling: 128 q x 64 keys, 8 warps (1 m16 each), stride 72 halfs (144B)
#define FS_STRIDE 144
#define FS_TILE_B (64 * FS_STRIDE)
#define FS_STAGE_B (4 * FS_TILE_B)
#define FLASH_SMEM (2 * FS_STAGE_B)            // 73728 B

// ---------------- scratch (device globals: no allocations allowed) ----------
__device__ __align__(256) __nv_bfloat16 g_xhi[NB * NT * ND];
__device__ __align__(256) __nv_bfloat16 g_xlo[NB * NT * ND];
__device__ __align__(256) __nv_bfloat16 g_khi[NB * TK * ND];   // pooled stream
__device__ __align__(256) __nv_bfloat16 g_klo[NB * TK * ND];
__device__ __align__(256) __nv_bfloat16 g_ohi[NB * NT * ND];   // attention out
__device__ __align__(256) __nv_bfloat16 g_olo[NB * NT * ND];
__device__ __align__(256) __nv_bfloat16 g_qh[NB * NT * ND], g_ql[NB * NT * ND];
__device__ __align__(256) __nv_bfloat16 g_kh[NB * TK * ND], g_kl[NB * TK * ND];
__device__ __align__(256) __nv_bfloat16 g_vh[NB * TK * ND], g_vl[NB * TK * ND];
__device__ __align__(256) __nv_bfloat16 g_wqhi[ND * ND], g_wqlo[ND * ND];
__device__ __align__(256) __nv_bfloat16 g_wkvhi[2 * ND * ND], g_wkvlo[2 * ND * ND];
__device__ __align__(256) __nv_bfloat16 g_wohi[ND * ND], g_wolo[ND * ND];
__device__ __align__(256) __nv_bfloat16 g_wchi[ND * 3 * ND], g_wclo[ND * 3 * ND];

// ---------------- PTX helpers ------------------------------------------------
__device__ __forceinline__ uint32_t smem_u32(const void* p) {
    uint32_t a;
    asm("{ .reg .u64 t; cvta.to.shared.u64 t, %1; cvt.u32.u64 %0, t; }" : "=r"(a) : "l"(p));
    return a;
}
__device__ __forceinline__ void cpa16(uint32_t dst, const void* src) {
    asm volatile("cp.async.cg.shared.global [%0], [%1], 16;" :: "r"(dst), "l"(src) : "memory");
}
__device__ __forceinline__ void ldsm4(uint32_t* r, uint32_t addr) {
    asm volatile("ldmatrix.sync.aligned.m8n8.x4.shared.b16 {%0,%1,%2,%3}, [%4];"
                 : "=r"(r[0]), "=r"(r[1]), "=r"(r[2]), "=r"(r[3]) : "r"(addr));
}
__device__ __forceinline__ void ldsm4t(uint32_t* r, uint32_t addr) {
    asm volatile("ldmatrix.sync.aligned.m8n8.x4.trans.shared.b16 {%0,%1,%2,%3}, [%4];"
                 : "=r"(r[0]), "=r"(r[1]), "=r"(r[2]), "=r"(r[3]) : "r"(addr));
}
__device__ __forceinline__ void mma16816(float* d, const uint32_t* a, uint32_t b0, uint32_t b1) {
    asm volatile("mma.sync.aligned.m16n8k16.row.col.f32.bf16.bf16.f32 "
                 "{%0,%1,%2,%3}, {%4,%5,%6,%7}, {%8,%9}, {%0,%1,%2,%3};"
                 : "+f"(d[0]), "+f"(d[1]), "+f"(d[2]), "+f"(d[3])
                 : "r"(a[0]), "r"(a[1]), "r"(a[2]), "r"(a[3]), "r"(b0), "r"(b1));
}
__device__ __forceinline__ uint32_t packbf(__nv_bfloat16 a, __nv_bfloat16 b) {
    __nv_bfloat162 t; t.x = a; t.y = b;
    return *(uint32_t*)&t;
}

// ---------------- conversion kernels ----------------------------------------
__global__ void cvt_hilo_k(const float* __restrict__ s, __nv_bfloat16* __restrict__ h,
                           __nv_bfloat16* __restrict__ l, int n) {
    int i = blockIdx.x * 256 + threadIdx.x;
    if (i >= n) return;
    float x = s[i];
    __nv_bfloat16 hh = __float2bfloat16(x);
    h[i] = hh;
    l[i] = __float2bfloat16(x - __bfloat162float(hh));
}

// One fused kernel: Wq, Wk, Wv, Wo hi/lo, Wconv transpose hi/lo, row0 prepend.
#define NW (ND * ND)
__global__ void cvt_weights(const float* __restrict__ Wq, const float* __restrict__ Wk,
                            const float* __restrict__ Wv, const float* __restrict__ Wo,
                            const float* __restrict__ Wc, const float* __restrict__ x,
                            __nv_bfloat16* __restrict__ wqh, __nv_bfloat16* __restrict__ wql,
                            __nv_bfloat16* __restrict__ wkvh, __nv_bfloat16* __restrict__ wkvl,
                            __nv_bfloat16* __restrict__ woh, __nv_bfloat16* __restrict__ wol,
                            __nv_bfloat16* __restrict__ wch, __nv_bfloat16* __restrict__ wcl,
                            __nv_bfloat16* __restrict__ kph, __nv_bfloat16* __restrict__ kpl) {
    int idx = blockIdx.x * 256 + threadIdx.x;
    float v;
    __nv_bfloat16* ph;
    __nv_bfloat16* pl;
    if (idx < NW) {
        v = Wq[idx]; ph = wqh + idx; pl = wql + idx;
    } else if (idx < 2 * NW) {
        int i = idx - NW;
        v = Wk[i]; ph = wkvh + i; pl = wkvl + i;
    } else if (idx < 3 * NW) {
        int i = idx - 2 * NW;
        v = Wv[i]; ph = wkvh + NW + i; pl = wkvl + NW + i;
    } else if (idx < 4 * NW) {
        int i = idx - 3 * NW;
        v = Wo[i]; ph = woh + i; pl = wol + i;
    } else if (idx < 7 * NW) {
        int i = idx - 4 * NW;
        int o = i / (3 * ND);
        int r = i - o * 3 * ND;
        int kw = r >> 10, ii = r & 1023;
        v = Wc[(size_t)o * 3 * ND + (size_t)ii * 3 + kw];
        ph = wch + i; pl = wcl + i;
    } else if (idx < 7 * NW + NB * ND) {
        int i = idx - 7 * NW;
        int b = i >> 10, d = i & 1023;
        v = x[(size_t)b * NT * ND + d];
        ph = kph + (size_t)b * TK * ND + d;
        pl = kpl + (size_t)b * TK * ND + d;
    } else return;
    __nv_bfloat16 hh = __float2bfloat16(v);
    *ph = hh;
    *pl = __float2bfloat16(v - __bfloat162float(hh));
}
#define CVTW_TOTAL (7 * NW + NB * ND)

// ---------------- HMMA bf16x3 GEMM (512 thr, 4x4 warps, 3-stage) --------------
// C[m][n] = sum_k A[m][k]*W[n][k], ~fp32 via Ahi*Bhi + Ahi*Blo + Alo*Bhi.
// MODE 0: A rows contiguous stride K.  MODE 1 (conv): A row m -> x at
//   ((m>>10)*3072 + (m&1023)*3)*1024, K=3072.
// EPI 1: bf16 hi/lo + conv row remap +1. EPI 2: fp32+bias.
// EPI 3: bf16 hi/lo direct. EPI 4: split cols<1024 -> Chi/Clo, >=1024 -> C2h/C2l.
template <int MODE, int EPI>
__global__ void __launch_bounds__(GTHREADS, 1)
gemm_mma(const __nv_bfloat16* __restrict__ Ahi, const __nv_bfloat16* __restrict__ Alo,
         const __nv_bfloat16* __restrict__ Whi, const __nv_bfloat16* __restrict__ Wlo,
         float* __restrict__ Cf, __nv_bfloat16* __restrict__ Chi, __nv_bfloat16* __restrict__ Clo,
         __nv_bfloat16* __restrict__ C2h, __nv_bfloat16* __restrict__ C2l,
         const float* __restrict__ bias, int M, int K) {
    extern __shared__ __align__(128) __nv_bfloat16 sm[];
    uint32_t sb = smem_u32(sm);
    int tid = threadIdx.x;
    int bm = blockIdx.y * BM, bn = blockIdx.x * BN;
    int NKT = K / BKH;
    int lane = tid & 31, wid = tid >> 5;
    int wm = wid & 3, wn = wid >> 2;          // 4x4 warp grid, tile 32x32

    float acc[2][4][4];
#pragma unroll
    for (int i = 0; i < 2; i++)
#pragma unroll
        for (int j = 0; j < 4; j++)
#pragma unroll
            for (int v = 0; v < 4; v++) acc[i][j][v] = 0.f;

    auto load_stage = [&](int kt, int s) {
        int k0 = kt * BKH;
        uint32_t sbase = sb + (uint32_t)s * STAGE_HALFS * 2;
#pragma unroll
        for (int t = 0; t < 4; t++) {
            int q = tid + t * GTHREADS;
            int tile = q >> 9;
            int idx = q & 511;
            int r = idx >> 2, c = idx & 3;
            uint32_t dst = sbase + (uint32_t)tile * TILE_HALFS * 2 + r * 80 + c * 16;
            const __nv_bfloat16* src;
            if (tile < 2) {
                int row = bm + r;
                if (row > M - 1) row = M - 1;
                size_t off;
                if (MODE == 0) off = (size_t)row * K;
                else           off = ((size_t)(row >> 10) * NT + (size_t)(row & 1023) * 3) * ND;
                src = (tile ? Alo : Ahi) + off + k0 + c * 8;
            } else {
                src = (tile == 2 ? Whi : Wlo) + (size_t)(bn + r) * K + k0 + c * 8;
            }
            cpa16(dst, src);
        }
        asm volatile("cp.async.commit_group;" ::: "memory");
    };

    load_stage(0, 0);
    if (NKT > 1) load_stage(1, 1);

    int s_cur = 0;
    for (int kt = 0; kt < NKT; kt++) {
        if (kt + 2 < NKT) {
            int s2 = s_cur + 2; if (s2 >= NSTAGE) s2 -= NSTAGE;
            load_stage(kt + 2, s2);
            asm volatile("cp.async.wait_group 2;" ::: "memory");
        } else if (kt + 1 < NKT) {
            asm volatile("cp.async.wait_group 1;" ::: "memory");
        } else {
            asm volatile("cp.async.wait_group 0;" ::: "memory");
        }
        __syncthreads();

        uint32_t st  = sb + (uint32_t)s_cur * STAGE_HALFS * 2;
        uint32_t aHi = st;
        uint32_t aLo = st + TILE_HALFS * 2;
        uint32_t bHi = st + 2 * TILE_HALFS * 2;
        uint32_t bLo = st + 3 * TILE_HALFS * 2;

#pragma unroll
        for (int ks = 0; ks < 2; ks++) {
            uint32_t a_hi[2][4], a_lo[2][4];
            uint32_t aoff = (uint32_t)(wm * 32 + (lane & 15)) * 80 + ks * 32 + ((lane >> 4) << 4);
            ldsm4(a_hi[0], aHi + aoff);
            ldsm4(a_hi[1], aHi + aoff + 16 * 80);
            ldsm4(a_lo[0], aLo + aoff);
            ldsm4(a_lo[1], aLo + aoff + 16 * 80);

            uint32_t boff = (uint32_t)((lane & 7) + ((lane >> 4) << 3)) * 80
                          + (((lane >> 3) & 1) << 4) + ks * 32;
#pragma unroll
            for (int j = 0; j < 2; j++) {              // two n16 blocks
                uint32_t b_hi[4], b_lo[4];
                uint32_t bo = boff + (uint32_t)(wn * 32 + j * 16) * 80;
                ldsm4(b_hi, bHi + bo);
                ldsm4(b_lo, bLo + bo);
#pragma unroll
                for (int p = 0; p < 2; p++) {
                    int nj = j * 2 + p;
#pragma unroll
                    for (int mi = 0; mi < 2; mi++) {
                        mma16816(acc[mi][nj], a_hi[mi], b_hi[p * 2], b_hi[p * 2 + 1]);
                        mma16816(acc[mi][nj], a_hi[mi], b_lo[p * 2], b_lo[p * 2 + 1]);
                        mma16816(acc[mi][nj], a_lo[mi], b_hi[p * 2], b_hi[p * 2 + 1]);
                    }
                }
            }
        }
        __syncthreads();
        if (++s_cur == NSTAGE) s_cur = 0;
    }

    int tq = lane >> 2, tr = lane & 3;
#pragma unroll
    for (int mi = 0; mi < 2; mi++) {
#pragma unroll
        for (int half = 0; half < 2; half++) {
            int row = bm + wm * 32 + mi * 16 + tq + half * 8;
            if (row >= M) continue;
#pragma unroll
            for (int nj = 0; nj < 4; nj++) {
                int col = bn + wn * 32 + nj * 8 + tr * 2;
                float v0 = acc[mi][nj][half * 2 + 0];
                float v1 = acc[mi][nj][half * 2 + 1];
                if (EPI == 1 || EPI == 3 || EPI == 4) {
                    __nv_bfloat16* ph;
                    __nv_bfloat16* pl;
                    if (EPI == 1) {
                        int orow = (row >> 10) * TK + (row & 1023) + 1;
                        ph = Chi + (size_t)orow * ND + col;
                        pl = Clo + (size_t)orow * ND + col;
                    } else if (EPI == 3) {
                        ph = Chi + (size_t)row * ND + col;
                        pl = Clo + (size_t)row * ND + col;
                    } else {
                        if (col < ND) {
                            ph = Chi + (size_t)row * ND + col;
                            pl = Clo + (size_t)row * ND + col;
                        } else {
                            ph = C2h + (size_t)row * ND + (col - ND);
                            pl = C2l + (size_t)row * ND + (col - ND);
                        }
                    }
                    __nv_bfloat16 h0 = __float2bfloat16(v0);
                    __nv_bfloat16 h1 = __float2bfloat16(v1);
                    *(uint32_t*)ph = packbf(h0, h1);
                    *(uint32_t*)pl = packbf(__float2bfloat16(v0 - __bfloat162float(h0)),
                                            __float2bfloat16(v1 - __bfloat162float(h1)));
                } else {
                    if (EPI == 2) { v0 += bias[col]; v1 += bias[col + 1]; }
                    float2 f2; f2.x = v0; f2.y = v1;
                    *(float2*)(Cf + (size_t)row * ND + col) = f2;
                }
            }
        }
    }
}

// ---------------- HMMA flash attention ---------------------------------------
// grid (24, 64): 128-q tile per CTA, 8 warps (one m16 each), 64-key tiles.
__global__ void __launch_bounds__(256, 1)
flash_mma(const __nv_bfloat16* __restrict__ Qh, const __nv_bfloat16* __restrict__ Ql,
          const __nv_bfloat16* __restrict__ Kh, const __nv_bfloat16* __restrict__ Kl,
          const __nv_bfloat16* __restrict__ Vh, const __nv_bfloat16* __restrict__ Vl,
          __nv_bfloat16* __restrict__ Ohi, __nv_bfloat16* __restrict__ Olo) {
    extern __shared__ __align__(128) char fsm[];
    uint32_t sb = smem_u32(fsm);
    int tid = threadIdx.x, lane = tid & 31, w = tid >> 5;
    int bh = blockIdx.y;
    int b = bh >> 4, h = bh & 15;
    int q0 = blockIdx.x * 128;

    const __nv_bfloat16* qhg = Qh + ((size_t)b * NT + q0) * ND + h * HD;
    const __nv_bfloat16* qlg = Ql + ((size_t)b * NT + q0) * ND + h * HD;
    const __nv_bfloat16* khg = Kh + (size_t)b * TK * ND + h * HD;
    const __nv_bfloat16* klg = Kl + (size_t)b * TK * ND + h * HD;
    const __nv_bfloat16* vhg = Vh + (size_t)b * TK * ND + h * HD;
    const __nv_bfloat16* vlg = Vl + (size_t)b * TK * ND + h * HD;

#pragma unroll
    for (int t = 0; t < 8; t++) {
        int idx = tid + (t & 3) * 256;
        int r = idx >> 3, c = idx & 7;
        const __nv_bfloat16* g = (t < 4) ? qhg : qlg;
        cpa16(sb + (t < 4 ? 0 : 18432) + r * FS_STRIDE + c * 16,
              g + (size_t)r * ND + c * 8);
    }
    asm volatile("cp.async.commit_group;" ::: "memory");
    asm volatile("cp.async.wait_group 0;" ::: "memory");
    __syncthreads();

    uint32_t qfh[4][4], qfl[4][4];
    {
        uint32_t aoff = (uint32_t)(w * 16 + (lane & 15)) * FS_STRIDE + ((lane >> 4) << 4);
#pragma unroll
        for (int kc = 0; kc < 4; kc++) {
            ldsm4(qfh[kc], sb + aoff + kc * 32);
            ldsm4(qfl[kc], sb + 18432 + aoff + kc * 32);
        }
    }
    __syncthreads();

    float m0 = -1e30f, m1 = -1e30f, l0 = 0.f, l1 = 0.f;
    float ao[8][4];
#pragma unroll
    for (int j = 0; j < 8; j++)
#pragma unroll
        for (int v = 0; v < 4; v++) ao[j][v] = 0.f;

    int kmax_blk = (q0 + 127) / 3;
    int ntiles = kmax_blk / 64 + 1;
    int qwmax = q0 + w * 16 + 15;
    int g8 = lane >> 2, tr2 = (lane & 3) * 2;
    int qa = q0 + w * 16 + g8, qb = qa + 8;

    auto load_kv = [&](int kt, int s) {
        uint32_t bse = sb + (uint32_t)s * FS_STAGE_B;
        size_t koff = (size_t)kt * 64 * ND;
#pragma unroll
        for (int t = 0; t < 8; t++) {
            int idx = tid + (t & 1) * 256;
            int r = idx >> 3, c = idx & 7;
            const __nv_bfloat16* g =
                (t < 2) ? khg : (t < 4) ? klg : (t < 6) ? vhg : vlg;
            cpa16(bse + (uint32_t)(t >> 1) * FS_TILE_B + r * FS_STRIDE + c * 16,
                  g + koff + (size_t)r * ND + c * 8);
        }
        asm volatile("cp.async.commit_group;" ::: "memory");
    };

    load_kv(0, 0);

    for (int kt = 0; kt < ntiles; kt++) {
        if (kt + 1 < ntiles) {
            load_kv(kt + 1, (kt + 1) & 1);
            asm volatile("cp.async.wait_group 1;" ::: "memory");
        } else {
            asm volatile("cp.async.wait_group 0;" ::: "memory");
        }
        __syncthreads();
        int kt0 = kt * 64;
        if (3 * kt0 <= qwmax) {
            uint32_t st = sb + (uint32_t)(kt & 1) * FS_STAGE_B;

            float sacc[8][4];
#pragma unroll
            for (int j = 0; j < 8; j++)
#pragma unroll
                for (int v = 0; v < 4; v++) sacc[j][v] = 0.f;

#pragma unroll
            for (int njp = 0; njp < 4; njp++) {
#pragma unroll
                for (int kc = 0; kc < 4; kc++) {
                    uint32_t boff = (uint32_t)(njp * 16 + (lane & 7) + ((lane >> 4) << 3)) * FS_STRIDE
                                  + kc * 32 + (((lane >> 3) & 1) << 4);
                    uint32_t bkh[4], bkl[4];
                    ldsm4(bkh, st + boff);
                    ldsm4(bkl, st + FS_TILE_B + boff);
#pragma unroll
                    for (int p = 0; p < 2; p++) {
                        mma16816(sacc[njp * 2 + p], qfh[kc], bkh[p * 2], bkh[p * 2 + 1]);
                        mma16816(sacc[njp * 2 + p], qfh[kc], bkl[p * 2], bkl[p * 2 + 1]);
                        mma16816(sacc[njp * 2 + p], qfl[kc], bkh[p * 2], bkh[p * 2 + 1]);
                    }
                }
            }

            float rm0 = -1e30f, rm1 = -1e30f;
#pragma unroll
            for (int nj = 0; nj < 8; nj++) {
                int key = kt0 + nj * 8 + tr2;
                float s0 = sacc[nj][0] * 0.125f; if (3 * key > qa) s0 = -1e30f;
                float s1 = sacc[nj][1] * 0.125f; if (3 * (key + 1) > qa) s1 = -1e30f;
                float s2 = sacc[nj][2] * 0.125f; if (3 * key > qb) s2 = -1e30f;
                float s3 = sacc[nj][3] * 0.125f; if (3 * (key + 1) > qb) s3 = -1e30f;
                sacc[nj][0] = s0; sacc[nj][1] = s1; sacc[nj][2] = s2; sacc[nj][3] = s3;
                rm0 = fmaxf(rm0, fmaxf(s0, s1));
                rm1 = fmaxf(rm1, fmaxf(s2, s3));
            }
            rm0 = fmaxf(rm0, __shfl_xor_sync(0xffffffffu, rm0, 1));
            rm0 = fmaxf(rm0, __shfl_xor_sync(0xffffffffu, rm0, 2));
            rm1 = fmaxf(rm1, __shfl_xor_sync(0xffffffffu, rm1, 1));
            rm1 = fmaxf(rm1, __shfl_xor_sync(0xffffffffu, rm1, 2));
            float nm0 = fmaxf(m0, rm0), nm1 = fmaxf(m1, rm1);
            float c0 = __expf(m0 - nm0), c1 = __expf(m1 - nm1);
            m0 = nm0; m1 = nm1;

            float ls0 = 0.f, ls1 = 0.f;
#pragma unroll
            for (int nj = 0; nj < 8; nj++) {
                float p0 = __expf(sacc[nj][0] - m0);
                float p1 = __expf(sacc[nj][1] - m0);
                float p2 = __expf(sacc[nj][2] - m1);
                float p3 = __expf(sacc[nj][3] - m1);
                sacc[nj][0] = p0; sacc[nj][1] = p1; sacc[nj][2] = p2; sacc[nj][3] = p3;
                ls0 += p0 + p1; ls1 += p2 + p3;
            }
            ls0 += __shfl_xor_sync(0xffffffffu, ls0, 1);
            ls0 += __shfl_xor_sync(0xffffffffu, ls0, 2);
            ls1 += __shfl_xor_sync(0xffffffffu, ls1, 1);
            ls1 += __shfl_xor_sync(0xffffffffu, ls1, 2);
            l0 = l0 * c0 + ls0;
            l1 = l1 * c1 + ls1;
#pragma unroll
            for (int nj = 0; nj < 8; nj++) {
                ao[nj][0] *= c0; ao[nj][1] *= c0;
                ao[nj][2] *= c1; ao[nj][3] *= c1;
            }

            uint32_t pah[4][4], pal[4][4];
#pragma unroll
            for (int kc = 0; kc < 4; kc++) {
#pragma unroll
                for (int rr = 0; rr < 4; rr++) {
                    int nj = kc * 2 + (rr >> 1);
                    int vb = (rr & 1) * 2;
                    float pa = sacc[nj][vb], pb = sacc[nj][vb + 1];
                    __nv_bfloat16 ha = __float2bfloat16(pa);
                    __nv_bfloat16 hb = __float2bfloat16(pb);
                    pah[kc][rr] = packbf(ha, hb);
                    pal[kc][rr] = packbf(__float2bfloat16(pa - __bfloat162float(ha)),
                                         __float2bfloat16(pb - __bfloat162float(hb)));
                }
            }

            uint32_t vbh = st + 2 * FS_TILE_B;
            uint32_t vbl = st + 3 * FS_TILE_B;
#pragma unroll
            for (int njp = 0; njp < 4; njp++) {
#pragma unroll
                for (int kc = 0; kc < 4; kc++) {
                    uint32_t voff = (uint32_t)(kc * 16 + (lane & 7) + (((lane >> 3) & 1) << 3)) * FS_STRIDE
                                  + (njp * 16 + (((lane >> 4) & 1) << 3)) * 2;
                    uint32_t bv[4], bw[4];
                    ldsm4t(bv, vbh + voff);
                    ldsm4t(bw, vbl + voff);
#pragma unroll
                    for (int p = 0; p < 2; p++) {
                        mma16816(ao[njp * 2 + p], pah[kc], bv[p * 2], bv[p * 2 + 1]);
                        mma16816(ao[njp * 2 + p], pal[kc], bv[p * 2], bv[p * 2 + 1]);
                        mma16816(ao[njp * 2 + p], pah[kc], bw[p * 2], bw[p * 2 + 1]);
                    }
                }
            }
        }
        __syncthreads();
    }

    float i0 = 1.f / l0, i1 = 1.f / l1;
    size_t rowa = ((size_t)b * NT + qa) * ND + h * HD;
    size_t rowb = rowa + (size_t)8 * ND;
#pragma unroll
    for (int nj = 0; nj < 8; nj++) {
        int col = nj * 8 + tr2;
        float v0 = ao[nj][0] * i0, v1 = ao[nj][1] * i0;
        float v2 = ao[nj][2] * i1, v3 = ao[nj][3] * i1;
        __nv_bfloat16 h0 = __float2bfloat16(v0), h1 = __float2bfloat16(v1);
        __nv_bfloat16 h2 = __float2bfloat16(v2), h3 = __float2bfloat16(v3);
        *(uint32_t*)(Ohi + rowa + col) = packbf(h0, h1);
        *(uint32_t*)(Olo + rowa + col) = packbf(__float2bfloat16(v0 - __bfloat162float(h0)),
                                                __float2bfloat16(v1 - __bfloat162float(h1)));
        *(uint32_t*)(Ohi + rowb + col) = packbf(h2, h3);
        *(uint32_t*)(Olo + rowb + col) = packbf(__float2bfloat16(v2 - __bfloat162float(h2)),
                                                __float2bfloat16(v3 - __bfloat162float(h3)));
    }
}

// ---------------- launch ------------------------------------------------------
extern "C" void kernel_launch(void* const* d_in, const int* in_sizes, int n_in,
                              void* d_out, int out_size) {
    const float* x     = (const float*)d_in[0];
    const float* Wq    = (const float*)d_in[1];
    const float* Wk    = (const float*)d_in[2];
    const float* Wv    = (const float*)d_in[3];
    const float* Wo    = (const float*)d_in[4];
    const float* bo    = (const float*)d_in[5];
    const float* Wconv = (const float*)d_in[6];
    float* out = (float*)d_out;

    __nv_bfloat16 *xhi, *xlo, *khi, *klo, *ohi, *olo;
    __nv_bfloat16 *qh, *ql, *kh, *kl, *vh, *vl;
    __nv_bfloat16 *wqhi, *wqlo, *wkvhi, *wkvlo, *wohi, *wolo, *wchi, *wclo;
    cudaGetSymbolAddress((void**)&xhi, g_xhi);     cudaGetSymbolAddress((void**)&xlo, g_xlo);
    cudaGetSymbolAddress((void**)&khi, g_khi);     cudaGetSymbolAddress((void**)&klo, g_klo);
    cudaGetSymbolAddress((void**)&ohi, g_ohi);     cudaGetSymbolAddress((void**)&olo, g_olo);
    cudaGetSymbolAddress((void**)&qh, g_qh);       cudaGetSymbolAddress((void**)&ql, g_ql);
    cudaGetSymbolAddress((void**)&kh, g_kh);       cudaGetSymbolAddress((void**)&kl, g_kl);
    cudaGetSymbolAddress((void**)&vh, g_vh);       cudaGetSymbolAddress((void**)&vl, g_vl);
    cudaGetSymbolAddress((void**)&wqhi, g_wqhi);   cudaGetSymbolAddress((void**)&wqlo, g_wqlo);
    cudaGetSymbolAddress((void**)&wkvhi, g_wkvhi); cudaGetSymbolAddress((void**)&wkvlo, g_wkvlo);
    cudaGetSymbolAddress((void**)&wohi, g_wohi);   cudaGetSymbolAddress((void**)&wolo, g_wolo);
    cudaGetSymbolAddress((void**)&wchi, g_wchi);   cudaGetSymbolAddress((void**)&wclo, g_wclo);

    cudaFuncSetAttribute(gemm_mma<1, 1>, cudaFuncAttributeMaxDynamicSharedMemorySize, GEMM_SMEM);
    cudaFuncSetAttribute(gemm_mma<0, 2>, cudaFuncAttributeMaxDynamicSharedMemorySize, GEMM_SMEM);
    cudaFuncSetAttribute(gemm_mma<0, 3>, cudaFuncAttributeMaxDynamicSharedMemorySize, GEMM_SMEM);
    cudaFuncSetAttribute(gemm_mma<0, 4>, cudaFuncAttributeMaxDynamicSharedMemorySize, GEMM_SMEM);
    cudaFuncSetAttribute(flash_mma, cudaFuncAttributeMaxDynamicSharedMemorySize, FLASH_SMEM);

    // 1. hi/lo conversions (x separate; everything else fused)
    int nx = NB * NT * ND;
    cvt_hilo_k<<<(nx + 255) / 256, 256>>>(x, xhi, xlo, nx);
    cvt_weights<<<(CVTW_TOTAL + 255) / 256, 256>>>(Wq, Wk, Wv, Wo, Wconv, x,
                                                   wqhi, wqlo, wkvhi, wkvlo,
                                                   wohi, wolo, wchi, wclo, khi, klo);

    // 2. conv pooling as GEMM -> ktmp hi/lo (rows 1..1024 per batch)
    gemm_mma<1, 1><<<dim3(8, 32), GTHREADS, GEMM_SMEM>>>(xhi, xlo, wchi, wclo,
        nullptr, khi, klo, nullptr, nullptr, nullptr, NB * ND, 3 * ND);

    // 3. Q projection -> qh/ql
    gemm_mma<0, 3><<<dim3(8, 96), GTHREADS, GEMM_SMEM>>>(xhi, xlo, wqhi, wqlo,
        nullptr, qh, ql, nullptr, nullptr, nullptr, NB * NT, ND);

    // 4. fused K+V projection (N=2048) -> kh/kl and vh/vl
    gemm_mma<0, 4><<<dim3(16, 33), GTHREADS, GEMM_SMEM>>>(khi, klo, wkvhi, wkvlo,
        nullptr, kh, kl, vh, vl, nullptr, NB * TK, ND);

    // 5. HMMA masked flash attention -> o hi/lo
    flash_mma<<<dim3(NT / 128, NB * NH), 256, FLASH_SMEM>>>(qh, ql, kh, kl, vh, vl, ohi, olo);

    // 6. output projection + bias -> d_out
    gemm_mma<0, 2><<<dim3(8, 96), GTHREADS, GEMM_SMEM>>>(ohi, olo, wohi, wolo,
        out, nullptr, nullptr, nullptr, nullptr, bo, NB * NT, ND);
}

// round 12
// speedup vs baseline: 1.4139x; 1.4139x over previous
#include <cuda_runtime.h>
#include <cuda_fp16.h>
#include <cstdint>

#define NB 4
#define NT 3072
#define ND 1024
#define NH 16
#define HD 64
#define TK 1025   // pooled K/V length: 1 + 3072/3

// GEMM tiling: 128x128 CTA tile, BK=32 halfs, 8 warps (4M x 2N), warp tile 32x64
#define BM 128
#define BN 128
#define BKH 32
#define TSTRIDE 40
#define TILE_HALFS (128 * TSTRIDE)
#define STAGE_HALFS (3 * TILE_HALFS)           // Ah, Al, Bh
#define NSTAGE 3
#define GEMM_SMEM (NSTAGE * STAGE_HALFS * 2)   // 92160 B
#define GTHREADS 256

// Flash tiling: 128 q x 64 keys, 8 warps (1 m16 each), stride 72 halfs (144B)
#define FS_STRIDE 144
#define FS_TILE_B (64 * FS_STRIDE)             // 9216 B (64x64 fp16 tile)
#define FS_STAGE_B (2 * FS_TILE_B)             // Kh + Vh = 18432
#define FLASH_SMEM (2 * FS_STAGE_B)            // 36864 B (also covers Q staging)

// ---------------- scratch (device globals: no allocations allowed) ----------
__device__ __align__(256) __half g_xh[NB * NT * ND], g_xl[NB * NT * ND];
__device__ __align__(256) __half g_kth[NB * TK * ND], g_ktl[NB * TK * ND];  // pooled
__device__ __align__(256) __half g_oh[NB * NT * ND], g_ol[NB * NT * ND];    // attn out
__device__ __align__(256) __half g_qh[NB * NT * ND], g_ql[NB * NT * ND];
__device__ __align__(256) __half g_kh[NB * TK * ND];    // 1-limb K
__device__ __align__(256) __half g_vh[NB * TK * ND];    // 1-limb V
__device__ __align__(256) __half g_wq[ND * ND];
__device__ __align__(256) __half g_wkv[2 * ND * ND];    // Wk rows 0-1023, Wv 1024-2047
__device__ __align__(256) __half g_wo[ND * ND];
__device__ __align__(256) __half g_wc[ND * 3 * ND];     // Wconv transposed

// ---------------- PTX helpers ------------------------------------------------
__device__ __forceinline__ uint32_t smem_u32(const void* p) {
    uint32_t a;
    asm("{ .reg .u64 t; cvta.to.shared.u64 t, %1; cvt.u32.u64 %0, t; }" : "=r"(a) : "l"(p));
    return a;
}
__device__ __forceinline__ void cpa16(uint32_t dst, const void* src) {
    asm volatile("cp.async.cg.shared.global [%0], [%1], 16;" :: "r"(dst), "l"(src) : "memory");
}
__device__ __forceinline__ void ldsm4(uint32_t* r, uint32_t addr) {
    asm volatile("ldmatrix.sync.aligned.m8n8.x4.shared.b16 {%0,%1,%2,%3}, [%4];"
                 : "=r"(r[0]), "=r"(r[1]), "=r"(r[2]), "=r"(r[3]) : "r"(addr));
}
__device__ __forceinline__ void ldsm4t(uint32_t* r, uint32_t addr) {
    asm volatile("ldmatrix.sync.aligned.m8n8.x4.trans.shared.b16 {%0,%1,%2,%3}, [%4];"
                 : "=r"(r[0]), "=r"(r[1]), "=r"(r[2]), "=r"(r[3]) : "r"(addr));
}
__device__ __forceinline__ void mmah(float* d, const uint32_t* a, uint32_t b0, uint32_t b1) {
    asm volatile("mma.sync.aligned.m16n8k16.row.col.f32.f16.f16.f32 "
                 "{%0,%1,%2,%3}, {%4,%5,%6,%7}, {%8,%9}, {%0,%1,%2,%3};"
                 : "+f"(d[0]), "+f"(d[1]), "+f"(d[2]), "+f"(d[3])
                 : "r"(a[0]), "r"(a[1]), "r"(a[2]), "r"(a[3]), "r"(b0), "r"(b1));
}
__device__ __forceinline__ uint32_t packh(__half a, __half b) {
    __half2 t = __halves2half2(a, b);
    return *(uint32_t*)&t;
}

// ---------------- conversion kernels ----------------------------------------
__global__ void cvt_hilo_h(const float* __restrict__ s, __half* __restrict__ h,
                           __half* __restrict__ l, int n) {
    int i = blockIdx.x * 256 + threadIdx.x;
    if (i >= n) return;
    float x = s[i];
    __half hh = __float2half_rn(x);
    h[i] = hh;
    l[i] = __float2half_rn(x - __half2float(hh));
}

// One fused kernel: Wq, Wk, Wv, Wo, Wconv-transpose (1-limb), row0 prepend (2-limb).
#define NW (ND * ND)
__global__ void cvt_weights(const float* __restrict__ Wq, const float* __restrict__ Wk,
                            const float* __restrict__ Wv, const float* __restrict__ Wo,
                            const float* __restrict__ Wc, const float* __restrict__ x,
                            __half* __restrict__ wq, __half* __restrict__ wkv,
                            __half* __restrict__ wo, __half* __restrict__ wc,
                            __half* __restrict__ kth, __half* __restrict__ ktl) {
    int idx = blockIdx.x * 256 + threadIdx.x;
    float v;
    __half* ph;
    __half* pl = nullptr;
    if (idx < NW) {
        v = Wq[idx]; ph = wq + idx;
    } else if (idx < 2 * NW) {
        int i = idx - NW;
        v = Wk[i]; ph = wkv + i;
    } else if (idx < 3 * NW) {
        int i = idx - 2 * NW;
        v = Wv[i]; ph = wkv + NW + i;
    } else if (idx < 4 * NW) {
        int i = idx - 3 * NW;
        v = Wo[i]; ph = wo + i;
    } else if (idx < 7 * NW) {
        int i = idx - 4 * NW;
        int o = i / (3 * ND);
        int r = i - o * 3 * ND;
        int kw = r >> 10, ii = r & 1023;
        v = Wc[(size_t)o * 3 * ND + (size_t)ii * 3 + kw];
        ph = wc + i;
    } else if (idx < 7 * NW + NB * ND) {
        int i = idx - 7 * NW;
        int b = i >> 10, d = i & 1023;
        v = x[(size_t)b * NT * ND + d];
        ph = kth + (size_t)b * TK * ND + d;
        pl = ktl + (size_t)b * TK * ND + d;
    } else return;
    __half hh = __float2half_rn(v);
    *ph = hh;
    if (pl) *pl = __float2half_rn(v - __half2float(hh));
}
#define CVTW_TOTAL (7 * NW + NB * ND)

// ---------------- HMMA fp16x2 GEMM (256 thr, 4x2 warps, 3-stage) --------------
// C[m][n] = sum_k A[m][k]*W[n][k], ~fp29xfp16 via Ah*Bh + Al*Bh (2 MMAs).
// MODE 0: A rows contiguous stride K.  MODE 1 (conv): A row m -> x at
//   ((m>>10)*3072 + (m&1023)*3)*1024, K=3072.
// EPI 1: half hi/lo + conv row remap +1. EPI 2: fp32+bias.
// EPI 3: half hi/lo direct. EPI 4: hi-only split cols<1024 -> Chi, >=1024 -> C2h.
template <int MODE, int EPI>
__global__ void __launch_bounds__(GTHREADS, 1)
gemm_mma(const __half* __restrict__ Ahi, const __half* __restrict__ Alo,
         const __half* __restrict__ Whi,
         float* __restrict__ Cf, __half* __restrict__ Chi, __half* __restrict__ Clo,
         __half* __restrict__ C2h,
         const float* __restrict__ bias, int M, int K) {
    extern __shared__ __align__(128) __half sm[];
    uint32_t sb = smem_u32(sm);
    int tid = threadIdx.x;
    int bm = blockIdx.y * BM, bn = blockIdx.x * BN;
    int NKT = K / BKH;
    int lane = tid & 31, wid = tid >> 5;
    int wm = wid & 3, wn = wid >> 2;          // 4x2 warp grid, tile 32x64

    float acc[2][8][4];
#pragma unroll
    for (int i = 0; i < 2; i++)
#pragma unroll
        for (int j = 0; j < 8; j++)
#pragma unroll
            for (int v = 0; v < 4; v++) acc[i][j][v] = 0.f;

    auto load_stage = [&](int kt, int s) {
        int k0 = kt * BKH;
        uint32_t sbase = sb + (uint32_t)s * STAGE_HALFS * 2;
#pragma unroll
        for (int t = 0; t < 6; t++) {          // 1536 chunks / 256 thr
            int q = tid + t * GTHREADS;
            int tile = q >> 9;                 // 0=Ah 1=Al 2=Bh
            int idx = q & 511;
            int r = idx >> 2, c = idx & 3;
            uint32_t dst = sbase + (uint32_t)tile * TILE_HALFS * 2 + r * 80 + c * 16;
            const __half* src;
            if (tile < 2) {
                int row = bm + r;
                if (row > M - 1) row = M - 1;
                size_t off;
                if (MODE == 0) off = (size_t)row * K;
                else           off = ((size_t)(row >> 10) * NT + (size_t)(row & 1023) * 3) * ND;
                src = (tile ? Alo : Ahi) + off + k0 + c * 8;
            } else {
                src = Whi + (size_t)(bn + r) * K + k0 + c * 8;
            }
            cpa16(dst, src);
        }
        asm volatile("cp.async.commit_group;" ::: "memory");
    };

    load_stage(0, 0);
    if (NKT > 1) load_stage(1, 1);

    int s_cur = 0;
    for (int kt = 0; kt < NKT; kt++) {
        if (kt + 2 < NKT) {
            int s2 = s_cur + 2; if (s2 >= NSTAGE) s2 -= NSTAGE;
            load_stage(kt + 2, s2);
            asm volatile("cp.async.wait_group 2;" ::: "memory");
        } else if (kt + 1 < NKT) {
            asm volatile("cp.async.wait_group 1;" ::: "memory");
        } else {
            asm volatile("cp.async.wait_group 0;" ::: "memory");
        }
        __syncthreads();

        uint32_t st  = sb + (uint32_t)s_cur * STAGE_HALFS * 2;
        uint32_t aHi = st;
        uint32_t aLo = st + TILE_HALFS * 2;
        uint32_t bHi = st + 2 * TILE_HALFS * 2;

#pragma unroll
        for (int ks = 0; ks < 2; ks++) {
            uint32_t a_hi[2][4], a_lo[2][4];
            uint32_t aoff = (uint32_t)(wm * 32 + (lane & 15)) * 80 + ks * 32 + ((lane >> 4) << 4);
            ldsm4(a_hi[0], aHi + aoff);
            ldsm4(a_hi[1], aHi + aoff + 16 * 80);
            ldsm4(a_lo[0], aLo + aoff);
            ldsm4(a_lo[1], aLo + aoff + 16 * 80);

            uint32_t boff = (uint32_t)((lane & 7) + ((lane >> 4) << 3)) * 80
                          + (((lane >> 3) & 1) << 4) + ks * 32;
#pragma unroll
            for (int j = 0; j < 4; j++) {
                uint32_t b_hi[4];
                uint32_t bo = boff + (uint32_t)(wn * 64 + j * 16) * 80;
                ldsm4(b_hi, bHi + bo);
#pragma unroll
                for (int p = 0; p < 2; p++) {
                    int nj = j * 2 + p;
#pragma unroll
                    for (int mi = 0; mi < 2; mi++) {
                        mmah(acc[mi][nj], a_hi[mi], b_hi[p * 2], b_hi[p * 2 + 1]);
                        mmah(acc[mi][nj], a_lo[mi], b_hi[p * 2], b_hi[p * 2 + 1]);
                    }
                }
            }
        }
        __syncthreads();
        if (++s_cur == NSTAGE) s_cur = 0;
    }

    int tq = lane >> 2, tr = lane & 3;
#pragma unroll
    for (int mi = 0; mi < 2; mi++) {
#pragma unroll
        for (int half = 0; half < 2; half++) {
            int row = bm + wm * 32 + mi * 16 + tq + half * 8;
            if (row >= M) continue;
#pragma unroll
            for (int nj = 0; nj < 8; nj++) {
                int col = bn + wn * 64 + nj * 8 + tr * 2;
                float v0 = acc[mi][nj][half * 2 + 0];
                float v1 = acc[mi][nj][half * 2 + 1];
                if (EPI == 1 || EPI == 3) {
                    int orow = (EPI == 1) ? ((row >> 10) * TK + (row & 1023) + 1) : row;
                    __half h0 = __float2half_rn(v0);
                    __half h1 = __float2half_rn(v1);
                    *(uint32_t*)(Chi + (size_t)orow * ND + col) = packh(h0, h1);
                    *(uint32_t*)(Clo + (size_t)orow * ND + col) =
                        packh(__float2half_rn(v0 - __half2float(h0)),
                              __float2half_rn(v1 - __half2float(h1)));
                } else if (EPI == 4) {
                    __half* ph = (col < ND) ? (Chi + (size_t)row * ND + col)
                                            : (C2h + (size_t)row * ND + (col - ND));
                    *(uint32_t*)ph = packh(__float2half_rn(v0), __float2half_rn(v1));
                } else {
                    if (EPI == 2) { v0 += bias[col]; v1 += bias[col + 1]; }
                    float2 f2; f2.x = v0; f2.y = v1;
                    *(float2*)(Cf + (size_t)row * ND + col) = f2;
                }
            }
        }
    }
}

// ---------------- HMMA flash attention (fp16x2) -------------------------------
// grid (24, 64): 128-q tile per CTA, 8 warps (one m16 each), 64-key tiles.
// S = Qh K + Ql K (2 mma); P split hi/lo fp16; O += Ph V + Pl V (2 mma).
__global__ void __launch_bounds__(256, 1)
flash_mma(const __half* __restrict__ Qh, const __half* __restrict__ Ql,
          const __half* __restrict__ Kh, const __half* __restrict__ Vh,
          __half* __restrict__ Oh, __half* __restrict__ Ol) {
    extern __shared__ __align__(128) char fsm[];
    uint32_t sb = smem_u32(fsm);
    int tid = threadIdx.x, lane = tid & 31, w = tid >> 5;
    int bh = blockIdx.y;
    int b = bh >> 4, h = bh & 15;
    int q0 = blockIdx.x * 128;

    const __half* qhg = Qh + ((size_t)b * NT + q0) * ND + h * HD;
    const __half* qlg = Ql + ((size_t)b * NT + q0) * ND + h * HD;
    const __half* khg = Kh + (size_t)b * TK * ND + h * HD;
    const __half* vhg = Vh + (size_t)b * TK * ND + h * HD;

    // ---- stage Q (128x64 hi/lo) into smem, extract A fragments -------------
#pragma unroll
    for (int t = 0; t < 8; t++) {
        int idx = tid + (t & 3) * 256;          // 0..1023
        int r = idx >> 3, c = idx & 7;
        const __half* g = (t < 4) ? qhg : qlg;
        cpa16(sb + (t < 4 ? 0 : 18432) + r * FS_STRIDE + c * 16,
              g + (size_t)r * ND + c * 8);
    }
    asm volatile("cp.async.commit_group;" ::: "memory");
    asm volatile("cp.async.wait_group 0;" ::: "memory");
    __syncthreads();

    uint32_t qfh[4][4], qfl[4][4];
    {
        uint32_t aoff = (uint32_t)(w * 16 + (lane & 15)) * FS_STRIDE + ((lane >> 4) << 4);
#pragma unroll
        for (int kc = 0; kc < 4; kc++) {
            ldsm4(qfh[kc], sb + aoff + kc * 32);
            ldsm4(qfl[kc], sb + 18432 + aoff + kc * 32);
        }
    }
    __syncthreads();

    float m0 = -1e30f, m1 = -1e30f, l0 = 0.f, l1 = 0.f;
    float ao[8][4];
#pragma unroll
    for (int j = 0; j < 8; j++)
#pragma unroll
        for (int v = 0; v < 4; v++) ao[j][v] = 0.f;

    int kmax_blk = (q0 + 127) / 3;
    int ntiles = kmax_blk / 64 + 1;
    int qwmax = q0 + w * 16 + 15;
    int g8 = lane >> 2, tr2 = (lane & 3) * 2;
    int qa = q0 + w * 16 + g8, qb = qa + 8;

    auto load_kv = [&](int kt, int s) {
        uint32_t bse = sb + (uint32_t)s * FS_STAGE_B;
        size_t koff = (size_t)kt * 64 * ND;
#pragma unroll
        for (int t = 0; t < 4; t++) {           // Kh: t 0,1  Vh: t 2,3
            int idx = tid + (t & 1) * 256;      // 0..511
            int r = idx >> 3, c = idx & 7;
            const __half* g = (t < 2) ? khg : vhg;
            cpa16(bse + (uint32_t)(t >> 1) * FS_TILE_B + r * FS_STRIDE + c * 16,
                  g + koff + (size_t)r * ND + c * 8);
        }
        asm volatile("cp.async.commit_group;" ::: "memory");
    };

    load_kv(0, 0);

    for (int kt = 0; kt < ntiles; kt++) {
        if (kt + 1 < ntiles) {
            load_kv(kt + 1, (kt + 1) & 1);
            asm volatile("cp.async.wait_group 1;" ::: "memory");
        } else {
            asm volatile("cp.async.wait_group 0;" ::: "memory");
        }
        __syncthreads();
        int kt0 = kt * 64;
        if (3 * kt0 <= qwmax) {
            uint32_t st = sb + (uint32_t)(kt & 1) * FS_STAGE_B;

            // ---- S = Q K^T (fp16x2) ----------------------------------------
            float sacc[8][4];
#pragma unroll
            for (int j = 0; j < 8; j++)
#pragma unroll
                for (int v = 0; v < 4; v++) sacc[j][v] = 0.f;

#pragma unroll
            for (int njp = 0; njp < 4; njp++) {
#pragma unroll
                for (int kc = 0; kc < 4; kc++) {
                    uint32_t boff = (uint32_t)(njp * 16 + (lane & 7) + ((lane >> 4) << 3)) * FS_STRIDE
                                  + kc * 32 + (((lane >> 3) & 1) << 4);
                    uint32_t bkh[4];
                    ldsm4(bkh, st + boff);
#pragma unroll
                    for (int p = 0; p < 2; p++) {
                        mmah(sacc[njp * 2 + p], qfh[kc], bkh[p * 2], bkh[p * 2 + 1]);
                        mmah(sacc[njp * 2 + p], qfl[kc], bkh[p * 2], bkh[p * 2 + 1]);
                    }
                }
            }

            // ---- scale + mask + online softmax -----------------------------
            float rm0 = -1e30f, rm1 = -1e30f;
#pragma unroll
            for (int nj = 0; nj < 8; nj++) {
                int key = kt0 + nj * 8 + tr2;
                float s0 = sacc[nj][0] * 0.125f; if (3 * key > qa) s0 = -1e30f;
                float s1 = sacc[nj][1] * 0.125f; if (3 * (key + 1) > qa) s1 = -1e30f;
                float s2 = sacc[nj][2] * 0.125f; if (3 * key > qb) s2 = -1e30f;
                float s3 = sacc[nj][3] * 0.125f; if (3 * (key + 1) > qb) s3 = -1e30f;
                sacc[nj][0] = s0; sacc[nj][1] = s1; sacc[nj][2] = s2; sacc[nj][3] = s3;
                rm0 = fmaxf(rm0, fmaxf(s0, s1));
                rm1 = fmaxf(rm1, fmaxf(s2, s3));
            }
            rm0 = fmaxf(rm0, __shfl_xor_sync(0xffffffffu, rm0, 1));
            rm0 = fmaxf(rm0, __shfl_xor_sync(0xffffffffu, rm0, 2));
            rm1 = fmaxf(rm1, __shfl_xor_sync(0xffffffffu, rm1, 1));
            rm1 = fmaxf(rm1, __shfl_xor_sync(0xffffffffu, rm1, 2));
            float nm0 = fmaxf(m0, rm0), nm1 = fmaxf(m1, rm1);
            float c0 = __expf(m0 - nm0), c1 = __expf(m1 - nm1);
            m0 = nm0; m1 = nm1;

            float ls0 = 0.f, ls1 = 0.f;
#pragma unroll
            for (int nj = 0; nj < 8; nj++) {
                float p0 = __expf(sacc[nj][0] - m0);
                float p1 = __expf(sacc[nj][1] - m0);
                float p2 = __expf(sacc[nj][2] - m1);
                float p3 = __expf(sacc[nj][3] - m1);
                sacc[nj][0] = p0; sacc[nj][1] = p1; sacc[nj][2] = p2; sacc[nj][3] = p3;
                ls0 += p0 + p1; ls1 += p2 + p3;
            }
            ls0 += __shfl_xor_sync(0xffffffffu, ls0, 1);
            ls0 += __shfl_xor_sync(0xffffffffu, ls0, 2);
            ls1 += __shfl_xor_sync(0xffffffffu, ls1, 1);
            ls1 += __shfl_xor_sync(0xffffffffu, ls1, 2);
            l0 = l0 * c0 + ls0;
            l1 = l1 * c1 + ls1;
#pragma unroll
            for (int nj = 0; nj < 8; nj++) {
                ao[nj][0] *= c0; ao[nj][1] *= c0;
                ao[nj][2] *= c1; ao[nj][3] *= c1;
            }

            // ---- P -> fp16 hi/lo A fragments -------------------------------
            uint32_t pah[4][4], pal[4][4];
#pragma unroll
            for (int kc = 0; kc < 4; kc++) {
#pragma unroll
                for (int rr = 0; rr < 4; rr++) {
                    int nj = kc * 2 + (rr >> 1);
                    int vb = (rr & 1) * 2;
                    float pa = sacc[nj][vb], pb = sacc[nj][vb + 1];
                    __half ha = __float2half_rn(pa);
                    __half hb = __float2half_rn(pb);
                    pah[kc][rr] = packh(ha, hb);
                    pal[kc][rr] = packh(__float2half_rn(pa - __half2float(ha)),
                                        __float2half_rn(pb - __half2float(hb)));
                }
            }

            // ---- O += P V (fp16x2) -----------------------------------------
            uint32_t vbh = st + FS_TILE_B;
#pragma unroll
            for (int njp = 0; njp < 4; njp++) {
#pragma unroll
                for (int kc = 0; kc < 4; kc++) {
                    uint32_t voff = (uint32_t)(kc * 16 + (lane & 7) + (((lane >> 3) & 1) << 3)) * FS_STRIDE
                                  + (njp * 16 + (((lane >> 4) & 1) << 3)) * 2;
                    uint32_t bv[4];
                    ldsm4t(bv, vbh + voff);
#pragma unroll
                    for (int p = 0; p < 2; p++) {
                        mmah(ao[njp * 2 + p], pah[kc], bv[p * 2], bv[p * 2 + 1]);
                        mmah(ao[njp * 2 + p], pal[kc], bv[p * 2], bv[p * 2 + 1]);
                    }
                }
            }
        }
        __syncthreads();
    }

    // ---- write O hi/lo ------------------------------------------------------
    float i0 = 1.f / l0, i1 = 1.f / l1;
    size_t rowa = ((size_t)b * NT + qa) * ND + h * HD;
    size_t rowb = rowa + (size_t)8 * ND;
#pragma unroll
    for (int nj = 0; nj < 8; nj++) {
        int col = nj * 8 + tr2;
        float v0 = ao[nj][0] * i0, v1 = ao[nj][1] * i0;
        float v2 = ao[nj][2] * i1, v3 = ao[nj][3] * i1;
        __half h0 = __float2half_rn(v0), h1 = __float2half_rn(v1);
        __half h2 = __float2half_rn(v2), h3 = __float2half_rn(v3);
        *(uint32_t*)(Oh + rowa + col) = packh(h0, h1);
        *(uint32_t*)(Ol + rowa + col) = packh(__float2half_rn(v0 - __half2float(h0)),
                                              __float2half_rn(v1 - __half2float(h1)));
        *(uint32_t*)(Oh + rowb + col) = packh(h2, h3);
        *(uint32_t*)(Ol + rowb + col) = packh(__float2half_rn(v2 - __half2float(h2)),
                                              __float2half_rn(v3 - __half2float(h3)));
    }
}

// ---------------- launch ------------------------------------------------------
extern "C" void kernel_launch(void* const* d_in, const int* in_sizes, int n_in,
                              void* d_out, int out_size) {
    const float* x     = (const float*)d_in[0];
    const float* Wq    = (const float*)d_in[1];
    const float* Wk    = (const float*)d_in[2];
    const float* Wv    = (const float*)d_in[3];
    const float* Wo    = (const float*)d_in[4];
    const float* bo    = (const float*)d_in[5];
    const float* Wconv = (const float*)d_in[6];
    float* out = (float*)d_out;

    __half *xh, *xl, *kth, *ktl, *oh, *ol, *qh, *ql, *kh, *vh;
    __half *wq, *wkv, *wo, *wc;
    cudaGetSymbolAddress((void**)&xh, g_xh);   cudaGetSymbolAddress((void**)&xl, g_xl);
    cudaGetSymbolAddress((void**)&kth, g_kth); cudaGetSymbolAddress((void**)&ktl, g_ktl);
    cudaGetSymbolAddress((void**)&oh, g_oh);   cudaGetSymbolAddress((void**)&ol, g_ol);
    cudaGetSymbolAddress((void**)&qh, g_qh);   cudaGetSymbolAddress((void**)&ql, g_ql);
    cudaGetSymbolAddress((void**)&kh, g_kh);   cudaGetSymbolAddress((void**)&vh, g_vh);
    cudaGetSymbolAddress((void**)&wq, g_wq);   cudaGetSymbolAddress((void**)&wkv, g_wkv);
    cudaGetSymbolAddress((void**)&wo, g_wo);   cudaGetSymbolAddress((void**)&wc, g_wc);

    cudaFuncSetAttribute(gemm_mma<1, 1>, cudaFuncAttributeMaxDynamicSharedMemorySize, GEMM_SMEM);
    cudaFuncSetAttribute(gemm_mma<0, 2>, cudaFuncAttributeMaxDynamicSharedMemorySize, GEMM_SMEM);
    cudaFuncSetAttribute(gemm_mma<0, 3>, cudaFuncAttributeMaxDynamicSharedMemorySize, GEMM_SMEM);
    cudaFuncSetAttribute(gemm_mma<0, 4>, cudaFuncAttributeMaxDynamicSharedMemorySize, GEMM_SMEM);
    cudaFuncSetAttribute(flash_mma, cudaFuncAttributeMaxDynamicSharedMemorySize, FLASH_SMEM);

    // 1. hi/lo conversion of x; weights (1-limb) + ktmp row0 fused
    int nx = NB * NT * ND;
    cvt_hilo_h<<<(nx + 255) / 256, 256>>>(x, xh, xl, nx);
    cvt_weights<<<(CVTW_TOTAL + 255) / 256, 256>>>(Wq, Wk, Wv, Wo, Wconv, x,
                                                   wq, wkv, wo, wc, kth, ktl);

    // 2. conv pooling as GEMM -> ktmp hi/lo (rows 1..1024 per batch)
    gemm_mma<1, 1><<<dim3(8, 32), GTHREADS, GEMM_SMEM>>>(xh, xl, wc,
        nullptr, kth, ktl, nullptr, nullptr, NB * ND, 3 * ND);

    // 3. Q projection -> qh/ql (2-limb)
    gemm_mma<0, 3><<<dim3(8, 96), GTHREADS, GEMM_SMEM>>>(xh, xl, wq,
        nullptr, qh, ql, nullptr, nullptr, NB * NT, ND);

    // 4. fused K+V projection (N=2048) -> kh, vh (1-limb)
    gemm_mma<0, 4><<<dim3(16, 33), GTHREADS, GEMM_SMEM>>>(kth, ktl, wkv,
        nullptr, kh, nullptr, vh, nullptr, NB * TK, ND);

    // 5. HMMA masked flash attention -> o hi/lo
    flash_mma<<<dim3(NT / 128, NB * NH), 256, FLASH_SMEM>>>(qh, ql, kh, vh, oh, ol);

    // 6. output projection + bias -> d_out
    gemm_mma<0, 2><<<dim3(8, 96), GTHREADS, GEMM_SMEM>>>(oh, ol, wo,
        out, nullptr, nullptr, nullptr, bo, NB * NT, ND);
}

// round 14
// speedup vs baseline: 1.4730x; 1.0418x over previous
#include <cuda_runtime.h>
#include <cuda_fp16.h>
#include <cstdint>

#define NB 4
#define NT 3072
#define ND 1024
#define NH 16
#define HD 64
#define TK 1025   // pooled K/V length: 1 + 3072/3

// GEMM tiling: 128x128 CTA tile, BK=32 halfs, 8 warps (4M x 2N), warp tile 32x64
#define BM 128
#define BN 128
#define BKH 32
#define TILE_HALFS (128 * 40)
#define STAGE_HALFS (3 * TILE_HALFS)           // Ah, Al, Bh
#define NSTAGE 3
#define GEMM_SMEM (NSTAGE * STAGE_HALFS * 2)   // 92160 B
#define GTHREADS 256

// Flash tiling: 128 q x 64 keys, 8 warps (1 m16 each), stride 72 halfs (144B)
#define FS_STRIDE 144
#define FS_TILE_B (64 * FS_STRIDE)             // 9216 B (64x64 fp16 tile)
#define FS_STAGE_B (2 * FS_TILE_B)             // Kh + Vh = 18432
#define FLASH_SMEM (3 * FS_STAGE_B)            // 55296 B (3-stage; covers Q staging 36864)

// ---------------- scratch (device globals: no allocations allowed) ----------
__device__ __align__(256) __half g_xh[NB * NT * ND], g_xl[NB * NT * ND];
__device__ __align__(256) __half g_kth[NB * TK * ND], g_ktl[NB * TK * ND];  // pooled
__device__ __align__(256) __half g_oh[NB * NT * ND], g_ol[NB * NT * ND];    // attn out
__device__ __align__(256) __half g_qh[NB * NT * ND], g_ql[NB * NT * ND];
__device__ __align__(256) __half g_kh[NB * TK * ND];    // 1-limb K
__device__ __align__(256) __half g_vh[NB * TK * ND];    // 1-limb V
__device__ __align__(256) __half g_wq[ND * ND];
__device__ __align__(256) __half g_wkv[2 * ND * ND];    // Wk rows 0-1023, Wv 1024-2047
__device__ __align__(256) __half g_wo[ND * ND];
__device__ __align__(256) __half g_wc[ND * 3 * ND];     // Wconv transposed

// ---------------- PTX helpers ------------------------------------------------
__device__ __forceinline__ uint32_t smem_u32(const void* p) {
    uint32_t a;
    asm("{ .reg .u64 t; cvta.to.shared.u64 t, %1; cvt.u32.u64 %0, t; }" : "=r"(a) : "l"(p));
    return a;
}
__device__ __forceinline__ void cpa16(uint32_t dst, const void* src) {
    asm volatile("cp.async.cg.shared.global [%0], [%1], 16;" :: "r"(dst), "l"(src) : "memory");
}
__device__ __forceinline__ void ldsm4(uint32_t* r, uint32_t addr) {
    asm volatile("ldmatrix.sync.aligned.m8n8.x4.shared.b16 {%0,%1,%2,%3}, [%4];"
                 : "=r"(r[0]), "=r"(r[1]), "=r"(r[2]), "=r"(r[3]) : "r"(addr));
}
__device__ __forceinline__ void ldsm4t(uint32_t* r, uint32_t addr) {
    asm volatile("ldmatrix.sync.aligned.m8n8.x4.trans.shared.b16 {%0,%1,%2,%3}, [%4];"
                 : "=r"(r[0]), "=r"(r[1]), "=r"(r[2]), "=r"(r[3]) : "r"(addr));
}
__device__ __forceinline__ void mmah(float* d, const uint32_t* a, uint32_t b0, uint32_t b1) {
    asm volatile("mma.sync.aligned.m16n8k16.row.col.f32.f16.f16.f32 "
                 "{%0,%1,%2,%3}, {%4,%5,%6,%7}, {%8,%9}, {%0,%1,%2,%3};"
                 : "+f"(d[0]), "+f"(d[1]), "+f"(d[2]), "+f"(d[3])
                 : "r"(a[0]), "r"(a[1]), "r"(a[2]), "r"(a[3]), "r"(b0), "r"(b1));
}
__device__ __forceinline__ uint32_t packh(__half a, __half b) {
    __half2 t = __halves2half2(a, b);
    return *(uint32_t*)&t;
}

// ---------------- fused conversion kernel ------------------------------------
// x (2-limb), Wq/Wk/Wv/Wo/Wconv-transpose (1-limb), ktmp row0 prepend (2-limb).
#define NW (ND * ND)
#define NX (NB * NT * ND)
#define CVT_TOTAL (NX + 7 * NW + NB * ND)
__global__ void cvt_all(const float* __restrict__ x,
                        const float* __restrict__ Wq, const float* __restrict__ Wk,
                        const float* __restrict__ Wv, const float* __restrict__ Wo,
                        const float* __restrict__ Wc,
                        __half* __restrict__ xh, __half* __restrict__ xl,
                        __half* __restrict__ wq, __half* __restrict__ wkv,
                        __half* __restrict__ wo, __half* __restrict__ wc,
                        __half* __restrict__ kth, __half* __restrict__ ktl) {
    int idx = blockIdx.x * 256 + threadIdx.x;
    float v;
    __half* ph;
    __half* pl = nullptr;
    if (idx < NX) {
        v = x[idx]; ph = xh + idx; pl = xl + idx;
    } else {
        int j = idx - NX;
        if (j < NW) {
            v = Wq[j]; ph = wq + j;
        } else if (j < 2 * NW) {
            int i = j - NW;
            v = Wk[i]; ph = wkv + i;
        } else if (j < 3 * NW) {
            int i = j - 2 * NW;
            v = Wv[i]; ph = wkv + NW + i;
        } else if (j < 4 * NW) {
            int i = j - 3 * NW;
            v = Wo[i]; ph = wo + i;
        } else if (j < 7 * NW) {
            int i = j - 4 * NW;
            int o = i / (3 * ND);
            int r = i - o * 3 * ND;
            int kw = r >> 10, ii = r & 1023;
            v = Wc[(size_t)o * 3 * ND + (size_t)ii * 3 + kw];
            ph = wc + i;
        } else if (j < 7 * NW + NB * ND) {
            int i = j - 7 * NW;
            int b = i >> 10, d = i & 1023;
            v = x[(size_t)b * NT * ND + d];
            ph = kth + (size_t)b * TK * ND + d;
            pl = ktl + (size_t)b * TK * ND + d;
        } else return;
    }
    __half hh = __float2half_rn(v);
    *ph = hh;
    if (pl) *pl = __float2half_rn(v - __half2float(hh));
}

// ---------------- fused conv + Q projection GEMM ------------------------------
// blockIdx.y < 32 -> conv pooling GEMM (M=4096, K=3072, strided x view, ktmp out)
// blockIdx.y >= 32 -> Q projection    (M=12288, K=1024, direct, q out)
// fp16x2: C = Ah*Bh + Al*Bh. Single __syncthreads per k-tile (3-stage ring).
__global__ void __launch_bounds__(GTHREADS, 1)
gemm_convq(const __half* __restrict__ xh, const __half* __restrict__ xl,
           const __half* __restrict__ wc, const __half* __restrict__ wq,
           __half* __restrict__ kth, __half* __restrict__ ktl,
           __half* __restrict__ qhd, __half* __restrict__ qld) {
    extern __shared__ __align__(128) __half sm[];
    uint32_t sb = smem_u32(sm);
    int tid = threadIdx.x;
    bool conv = blockIdx.y < 32;
    int bm = conv ? blockIdx.y * BM : (blockIdx.y - 32) * BM;
    int bn = blockIdx.x * BN;
    int K = conv ? 3 * ND : ND;
    int NKT = K >> 5;
    const __half* W = conv ? wc : wq;
    int lane = tid & 31, wid = tid >> 5;
    int wm = wid & 3, wn = wid >> 2;

    float acc[2][8][4];
#pragma unroll
    for (int i = 0; i < 2; i++)
#pragma unroll
        for (int j = 0; j < 8; j++)
#pragma unroll
            for (int v = 0; v < 4; v++) acc[i][j][v] = 0.f;

    auto load_stage = [&](int kt, int s) {
        int k0 = kt * BKH;
        uint32_t sbase = sb + (uint32_t)s * STAGE_HALFS * 2;
#pragma unroll
        for (int t = 0; t < 6; t++) {
            int q = tid + t * GTHREADS;
            int tile = q >> 9;                 // 0=Ah 1=Al 2=Bh
            int idx = q & 511;
            int r = idx >> 2, c = idx & 3;
            uint32_t dst = sbase + (uint32_t)tile * TILE_HALFS * 2 + r * 80 + c * 16;
            const __half* src;
            if (tile < 2) {
                int row = bm + r;
                size_t off;
                if (conv) off = ((size_t)(row >> 10) * NT + (size_t)(row & 1023) * 3) * ND;
                else      off = (size_t)row * ND;
                src = (tile ? xl : xh) + off + k0 + c * 8;
            } else {
                src = W + (size_t)(bn + r) * K + k0 + c * 8;
            }
            cpa16(dst, src);
        }
        asm volatile("cp.async.commit_group;" ::: "memory");
    };

    load_stage(0, 0);
    load_stage(1, 1);

    int s_cur = 0;
    for (int kt = 0; kt < NKT; kt++) {
        if (kt + 1 < NKT) { asm volatile("cp.async.wait_group 1;" ::: "memory"); }
        else              { asm volatile("cp.async.wait_group 0;" ::: "memory"); }
        __syncthreads();
        if (kt + 2 < NKT) {
            int s2 = s_cur + 2; if (s2 >= NSTAGE) s2 -= NSTAGE;
            load_stage(kt + 2, s2);
        }

        uint32_t st  = sb + (uint32_t)s_cur * STAGE_HALFS * 2;
        uint32_t aHi = st;
        uint32_t aLo = st + TILE_HALFS * 2;
        uint32_t bHi = st + 2 * TILE_HALFS * 2;

#pragma unroll
        for (int ks = 0; ks < 2; ks++) {
            uint32_t a_hi[2][4], a_lo[2][4];
            uint32_t aoff = (uint32_t)(wm * 32 + (lane & 15)) * 80 + ks * 32 + ((lane >> 4) << 4);
            ldsm4(a_hi[0], aHi + aoff);
            ldsm4(a_hi[1], aHi + aoff + 16 * 80);
            ldsm4(a_lo[0], aLo + aoff);
            ldsm4(a_lo[1], aLo + aoff + 16 * 80);

            uint32_t boff = (uint32_t)((lane & 7) + ((lane >> 4) << 3)) * 80
                          + (((lane >> 3) & 1) << 4) + ks * 32;
#pragma unroll
            for (int j = 0; j < 4; j++) {
                uint32_t b_hi[4];
                uint32_t bo = boff + (uint32_t)(wn * 64 + j * 16) * 80;
                ldsm4(b_hi, bHi + bo);
#pragma unroll
                for (int p = 0; p < 2; p++) {
                    int nj = j * 2 + p;
#pragma unroll
                    for (int mi = 0; mi < 2; mi++) {
                        mmah(acc[mi][nj], a_hi[mi], b_hi[p * 2], b_hi[p * 2 + 1]);
                        mmah(acc[mi][nj], a_lo[mi], b_hi[p * 2], b_hi[p * 2 + 1]);
                    }
                }
            }
        }
        if (++s_cur == NSTAGE) s_cur = 0;
    }

    __half* Ch = conv ? kth : qhd;
    __half* Cl = conv ? ktl : qld;
    int tq = lane >> 2, tr = lane & 3;
#pragma unroll
    for (int mi = 0; mi < 2; mi++) {
#pragma unroll
        for (int half = 0; half < 2; half++) {
            int row = bm + wm * 32 + mi * 16 + tq + half * 8;
            int orow = conv ? ((row >> 10) * TK + (row & 1023) + 1) : row;
#pragma unroll
            for (int nj = 0; nj < 8; nj++) {
                int col = bn + wn * 64 + nj * 8 + tr * 2;
                float v0 = acc[mi][nj][half * 2 + 0];
                float v1 = acc[mi][nj][half * 2 + 1];
                __half h0 = __float2half_rn(v0);
                __half h1 = __float2half_rn(v1);
                *(uint32_t*)(Ch + (size_t)orow * ND + col) = packh(h0, h1);
                *(uint32_t*)(Cl + (size_t)orow * ND + col) =
                    packh(__float2half_rn(v0 - __half2float(h0)),
                          __float2half_rn(v1 - __half2float(h1)));
            }
        }
    }
}

// ---------------- HMMA fp16x2 GEMM (KV and Wo) --------------------------------
// EPI 2: fp32+bias out. EPI 4: hi-only split cols<1024 -> Chi, >=1024 -> C2h.
template <int EPI>
__global__ void __launch_bounds__(GTHREADS, 1)
gemm_mma(const __half* __restrict__ Ahi, const __half* __restrict__ Alo,
         const __half* __restrict__ Whi,
         float* __restrict__ Cf, __half* __restrict__ Chi, __half* __restrict__ C2h,
         const float* __restrict__ bias, int M, int K) {
    extern __shared__ __align__(128) __half sm[];
    uint32_t sb = smem_u32(sm);
    int tid = threadIdx.x;
    int bm = blockIdx.y * BM, bn = blockIdx.x * BN;
    int NKT = K >> 5;
    int lane = tid & 31, wid = tid >> 5;
    int wm = wid & 3, wn = wid >> 2;

    float acc[2][8][4];
#pragma unroll
    for (int i = 0; i < 2; i++)
#pragma unroll
        for (int j = 0; j < 8; j++)
#pragma unroll
            for (int v = 0; v < 4; v++) acc[i][j][v] = 0.f;

    auto load_stage = [&](int kt, int s) {
        int k0 = kt * BKH;
        uint32_t sbase = sb + (uint32_t)s * STAGE_HALFS * 2;
#pragma unroll
        for (int t = 0; t < 6; t++) {
            int q = tid + t * GTHREADS;
            int tile = q >> 9;
            int idx = q & 511;
            int r = idx >> 2, c = idx & 3;
            uint32_t dst = sbase + (uint32_t)tile * TILE_HALFS * 2 + r * 80 + c * 16;
            const __half* src;
            if (tile < 2) {
                int row = bm + r;
                if (row > M - 1) row = M - 1;
                src = (tile ? Alo : Ahi) + (size_t)row * K + k0 + c * 8;
            } else {
                src = Whi + (size_t)(bn + r) * K + k0 + c * 8;
            }
            cpa16(dst, src);
        }
        asm volatile("cp.async.commit_group;" ::: "memory");
    };

    load_stage(0, 0);
    load_stage(1, 1);

    int s_cur = 0;
    for (int kt = 0; kt < NKT; kt++) {
        if (kt + 1 < NKT) { asm volatile("cp.async.wait_group 1;" ::: "memory"); }
        else              { asm volatile("cp.async.wait_group 0;" ::: "memory"); }
        __syncthreads();
        if (kt + 2 < NKT) {
            int s2 = s_cur + 2; if (s2 >= NSTAGE) s2 -= NSTAGE;
            load_stage(kt + 2, s2);
        }

        uint32_t st  = sb + (uint32_t)s_cur * STAGE_HALFS * 2;
        uint32_t aHi = st;
        uint32_t aLo = st + TILE_HALFS * 2;
        uint32_t bHi = st + 2 * TILE_HALFS * 2;

#pragma unroll
        for (int ks = 0; ks < 2; ks++) {
            uint32_t a_hi[2][4], a_lo[2][4];
            uint32_t aoff = (uint32_t)(wm * 32 + (lane & 15)) * 80 + ks * 32 + ((lane >> 4) << 4);
            ldsm4(a_hi[0], aHi + aoff);
            ldsm4(a_hi[1], aHi + aoff + 16 * 80);
            ldsm4(a_lo[0], aLo + aoff);
            ldsm4(a_lo[1], aLo + aoff + 16 * 80);

            uint32_t boff = (uint32_t)((lane & 7) + ((lane >> 4) << 3)) * 80
                          + (((lane >> 3) & 1) << 4) + ks * 32;
#pragma unroll
            for (int j = 0; j < 4; j++) {
                uint32_t b_hi[4];
                uint32_t bo = boff + (uint32_t)(wn * 64 + j * 16) * 80;
                ldsm4(b_hi, bHi + bo);
#pragma unroll
                for (int p = 0; p < 2; p++) {
                    int nj = j * 2 + p;
#pragma unroll
                    for (int mi = 0; mi < 2; mi++) {
                        mmah(acc[mi][nj], a_hi[mi], b_hi[p * 2], b_hi[p * 2 + 1]);
                        mmah(acc[mi][nj], a_lo[mi], b_hi[p * 2], b_hi[p * 2 + 1]);
                    }
                }
            }
        }
        if (++s_cur == NSTAGE) s_cur = 0;
    }

    int tq = lane >> 2, tr = lane & 3;
#pragma unroll
    for (int mi = 0; mi < 2; mi++) {
#pragma unroll
        for (int half = 0; half < 2; half++) {
            int row = bm + wm * 32 + mi * 16 + tq + half * 8;
            if (row >= M) continue;
#pragma unroll
            for (int nj = 0; nj < 8; nj++) {
                int col = bn + wn * 64 + nj * 8 + tr * 2;
                float v0 = acc[mi][nj][half * 2 + 0];
                float v1 = acc[mi][nj][half * 2 + 1];
                if (EPI == 4) {
                    __half* ph = (col < ND) ? (Chi + (size_t)row * ND + col)
                                            : (C2h + (size_t)row * ND + (col - ND));
                    *(uint32_t*)ph = packh(__float2half_rn(v0), __float2half_rn(v1));
                } else {
                    v0 += bias[col]; v1 += bias[col + 1];
                    float2 f2; f2.x = v0; f2.y = v1;
                    *(float2*)(Cf + (size_t)row * ND + col) = f2;
                }
            }
        }
    }
}

// ---------------- HMMA flash attention (fp16x2, 3-stage, 1 sync/tile) ---------
__global__ void __launch_bounds__(256, 1)
flash_mma(const __half* __restrict__ Qh, const __half* __restrict__ Ql,
          const __half* __restrict__ Kh, const __half* __restrict__ Vh,
          __half* __restrict__ Oh, __half* __restrict__ Ol) {
    extern __shared__ __align__(128) char fsm[];
    uint32_t sb = smem_u32(fsm);
    int tid = threadIdx.x, lane = tid & 31, w = tid >> 5;
    int bh = blockIdx.y;
    int b = bh >> 4, h = bh & 15;
    int q0 = blockIdx.x * 128;

    const __half* qhg = Qh + ((size_t)b * NT + q0) * ND + h * HD;
    const __half* qlg = Ql + ((size_t)b * NT + q0) * ND + h * HD;
    const __half* khg = Kh + (size_t)b * TK * ND + h * HD;
    const __half* vhg = Vh + (size_t)b * TK * ND + h * HD;

    // ---- stage Q (128x64 hi/lo), extract A fragments ------------------------
#pragma unroll
    for (int t = 0; t < 8; t++) {
        int idx = tid + (t & 3) * 256;
        int r = idx >> 3, c = idx & 7;
        const __half* g = (t < 4) ? qhg : qlg;
        cpa16(sb + (t < 4 ? 0 : 18432) + r * FS_STRIDE + c * 16,
              g + (size_t)r * ND + c * 8);
    }
    asm volatile("cp.async.commit_group;" ::: "memory");
    asm volatile("cp.async.wait_group 0;" ::: "memory");
    __syncthreads();

    uint32_t qfh[4][4], qfl[4][4];
    {
        uint32_t aoff = (uint32_t)(w * 16 + (lane & 15)) * FS_STRIDE + ((lane >> 4) << 4);
#pragma unroll
        for (int kc = 0; kc < 4; kc++) {
            ldsm4(qfh[kc], sb + aoff + kc * 32);
            ldsm4(qfl[kc], sb + 18432 + aoff + kc * 32);
        }
    }
    __syncthreads();

    float m0 = -1e30f, m1 = -1e30f, l0 = 0.f, l1 = 0.f;
    float ao[8][4];
#pragma unroll
    for (int j = 0; j < 8; j++)
#pragma unroll
        for (int v = 0; v < 4; v++) ao[j][v] = 0.f;

    int kmax_blk = (q0 + 127) / 3;
    int ntiles = kmax_blk / 64 + 1;
    int qwmax = q0 + w * 16 + 15;
    int g8 = lane >> 2, tr2 = (lane & 3) * 2;
    int qa = q0 + w * 16 + g8, qb = qa + 8;

    auto load_kv = [&](int kt, int s) {
        uint32_t bse = sb + (uint32_t)s * FS_STAGE_B;
        size_t koff = (size_t)kt * 64 * ND;
#pragma unroll
        for (int t = 0; t < 4; t++) {
            int idx = tid + (t & 1) * 256;
            int r = idx >> 3, c = idx & 7;
            const __half* g = (t < 2) ? khg : vhg;
            cpa16(bse + (uint32_t)(t >> 1) * FS_TILE_B + r * FS_STRIDE + c * 16,
                  g + koff + (size_t)r * ND + c * 8);
        }
        asm volatile("cp.async.commit_group;" ::: "memory");
    };

    load_kv(0, 0);
    if (ntiles > 1) load_kv(1, 1);

    int s_cur = 0;
    for (int kt = 0; kt < ntiles; kt++) {
        if (kt + 1 < ntiles) { asm volatile("cp.async.wait_group 1;" ::: "memory"); }
        else                 { asm volatile("cp.async.wait_group 0;" ::: "memory"); }
        __syncthreads();
        if (kt + 2 < ntiles) {
            int s2 = s_cur + 2; if (s2 >= 3) s2 -= 3;
            load_kv(kt + 2, s2);
        }
        int kt0 = kt * 64;
        if (3 * kt0 <= qwmax) {
            uint32_t st = sb + (uint32_t)s_cur * FS_STAGE_B;

            // ---- S = Q K^T (fp16x2) ----------------------------------------
            float sacc[8][4];
#pragma unroll
            for (int j = 0; j < 8; j++)
#pragma unroll
                for (int v = 0; v < 4; v++) sacc[j][v] = 0.f;

#pragma unroll
            for (int njp = 0; njp < 4; njp++) {
#pragma unroll
                for (int kc = 0; kc < 4; kc++) {
                    uint32_t boff = (uint32_t)(njp * 16 + (lane & 7) + ((lane >> 4) << 3)) * FS_STRIDE
                                  + kc * 32 + (((lane >> 3) & 1) << 4);
                    uint32_t bkh[4];
                    ldsm4(bkh, st + boff);
#pragma unroll
                    for (int p = 0; p < 2; p++) {
                        mmah(sacc[njp * 2 + p], qfh[kc], bkh[p * 2], bkh[p * 2 + 1]);
                        mmah(sacc[njp * 2 + p], qfl[kc], bkh[p * 2], bkh[p * 2 + 1]);
                    }
                }
            }

            // ---- scale + mask + online softmax -----------------------------
            float rm0 = -1e30f, rm1 = -1e30f;
#pragma unroll
            for (int nj = 0; nj < 8; nj++) {
                int key = kt0 + nj * 8 + tr2;
                float s0 = sacc[nj][0] * 0.125f; if (3 * key > qa) s0 = -1e30f;
                float s1 = sacc[nj][1] * 0.125f; if (3 * (key + 1) > qa) s1 = -1e30f;
                float s2 = sacc[nj][2] * 0.125f; if (3 * key > qb) s2 = -1e30f;
                float s3 = sacc[nj][3] * 0.125f; if (3 * (key + 1) > qb) s3 = -1e30f;
                sacc[nj][0] = s0; sacc[nj][1] = s1; sacc[nj][2] = s2; sacc[nj][3] = s3;
                rm0 = fmaxf(rm0, fmaxf(s0, s1));
                rm1 = fmaxf(rm1, fmaxf(s2, s3));
            }
            rm0 = fmaxf(rm0, __shfl_xor_sync(0xffffffffu, rm0, 1));
            rm0 = fmaxf(rm0, __shfl_xor_sync(0xffffffffu, rm0, 2));
            rm1 = fmaxf(rm1, __shfl_xor_sync(0xffffffffu, rm1, 1));
            rm1 = fmaxf(rm1, __shfl_xor_sync(0xffffffffu, rm1, 2));
            float nm0 = fmaxf(m0, rm0), nm1 = fmaxf(m1, rm1);
            float c0 = __expf(m0 - nm0), c1 = __expf(m1 - nm1);
            m0 = nm0; m1 = nm1;

            float ls0 = 0.f, ls1 = 0.f;
#pragma unroll
            for (int nj = 0; nj < 8; nj++) {
                float p0 = __expf(sacc[nj][0] - m0);
                float p1 = __expf(sacc[nj][1] - m0);
                float p2 = __expf(sacc[nj][2] - m1);
                float p3 = __expf(sacc[nj][3] - m1);
                sacc[nj][0] = p0; sacc[nj][1] = p1; sacc[nj][2] = p2; sacc[nj][3] = p3;
                ls0 += p0 + p1; ls1 += p2 + p3;
            }
            ls0 += __shfl_xor_sync(0xffffffffu, ls0, 1);
            ls0 += __shfl_xor_sync(0xffffffffu, ls0, 2);
            ls1 += __shfl_xor_sync(0xffffffffu, ls1, 1);
            ls1 += __shfl_xor_sync(0xffffffffu, ls1, 2);
            l0 = l0 * c0 + ls0;
            l1 = l1 * c1 + ls1;
#pragma unroll
            for (int nj = 0; nj < 8; nj++) {
                ao[nj][0] *= c0; ao[nj][1] *= c0;
                ao[nj][2] *= c1; ao[nj][3] *= c1;
            }

            // ---- P -> fp16 hi/lo A fragments -------------------------------
            uint32_t pah[4][4], pal[4][4];
#pragma unroll
            for (int kc = 0; kc < 4; kc++) {
#pragma unroll
                for (int rr = 0; rr < 4; rr++) {
                    int nj = kc * 2 + (rr >> 1);
                    int vb = (rr & 1) * 2;
                    float pa = sacc[nj][vb], pb = sacc[nj][vb + 1];
                    __half ha = __float2half_rn(pa);
                    __half hb = __float2half_rn(pb);
                    pah[kc][rr] = packh(ha, hb);
                    pal[kc][rr] = packh(__float2half_rn(pa - __half2float(ha)),
                                        __float2half_rn(pb - __half2float(hb)));
                }
            }

            // ---- O += P V (fp16x2) -----------------------------------------
            uint32_t vbh = st + FS_TILE_B;
#pragma unroll
            for (int njp = 0; njp < 4; njp++) {
#pragma unroll
                for (int kc = 0; kc < 4; kc++) {
                    uint32_t voff = (uint32_t)(kc * 16 + (lane & 7) + (((lane >> 3) & 1) << 3)) * FS_STRIDE
                                  + (njp * 16 + (((lane >> 4) & 1) << 3)) * 2;
                    uint32_t bv[4];
                    ldsm4t(bv, vbh + voff);
#pragma unroll
                    for (int p = 0; p < 2; p++) {
                        mmah(ao[njp * 2 + p], pah[kc], bv[p * 2], bv[p * 2 + 1]);
                        mmah(ao[njp * 2 + p], pal[kc], bv[p * 2], bv[p * 2 + 1]);
                    }
                }
            }
        }
        if (++s_cur == 3) s_cur = 0;
    }

    // ---- write O hi/lo ------------------------------------------------------
    float i0 = 1.f / l0, i1 = 1.f / l1;
    size_t rowa = ((size_t)b * NT + qa) * ND + h * HD;
    size_t rowb = rowa + (size_t)8 * ND;
#pragma unroll
    for (int nj = 0; nj < 8; nj++) {
        int col = nj * 8 + tr2;
        float v0 = ao[nj][0] * i0, v1 = ao[nj][1] * i0;
        float v2 = ao[nj][2] * i1, v3 = ao[nj][3] * i1;
        __half h0 = __float2half_rn(v0), h1 = __float2half_rn(v1);
        __half h2 = __float2half_rn(v2), h3 = __float2half_rn(v3);
        *(uint32_t*)(Oh + rowa + col) = packh(h0, h1);
        *(uint32_t*)(Ol + rowa + col) = packh(__float2half_rn(v0 - __half2float(h0)),
                                              __float2half_rn(v1 - __half2float(h1)));
        *(uint32_t*)(Oh + rowb + col) = packh(h2, h3);
        *(uint32_t*)(Ol + rowb + col) = packh(__float2half_rn(v2 - __half2float(h2)),
                                              __float2half_rn(v3 - __half2float(h3)));
    }
}

// ---------------- launch ------------------------------------------------------
extern "C" void kernel_launch(void* const* d_in, const int* in_sizes, int n_in,
                              void* d_out, int out_size) {
    const float* x     = (const float*)d_in[0];
    const float* Wq    = (const float*)d_in[1];
    const float* Wk    = (const float*)d_in[2];
    const float* Wv    = (const float*)d_in[3];
    const float* Wo    = (const float*)d_in[4];
    const float* bo    = (const float*)d_in[5];
    const float* Wconv = (const float*)d_in[6];
    float* out = (float*)d_out;

    __half *xh, *xl, *kth, *ktl, *oh, *ol, *qh, *ql, *kh, *vh;
    __half *wq, *wkv, *wo, *wc;
    cudaGetSymbolAddress((void**)&xh, g_xh);   cudaGetSymbolAddress((void**)&xl, g_xl);
    cudaGetSymbolAddress((void**)&kth, g_kth); cudaGetSymbolAddress((void**)&ktl, g_ktl);
    cudaGetSymbolAddress((void**)&oh, g_oh);   cudaGetSymbolAddress((void**)&ol, g_ol);
    cudaGetSymbolAddress((void**)&qh, g_qh);   cudaGetSymbolAddress((void**)&ql, g_ql);
    cudaGetSymbolAddress((void**)&kh, g_kh);   cudaGetSymbolAddress((void**)&vh, g_vh);
    cudaGetSymbolAddress((void**)&wq, g_wq);   cudaGetSymbolAddress((void**)&wkv, g_wkv);
    cudaGetSymbolAddress((void**)&wo, g_wo);   cudaGetSymbolAddress((void**)&wc, g_wc);

    cudaFuncSetAttribute(gemm_convq,  cudaFuncAttributeMaxDynamicSharedMemorySize, GEMM_SMEM);
    cudaFuncSetAttribute(gemm_mma<2>, cudaFuncAttributeMaxDynamicSharedMemorySize, GEMM_SMEM);
    cudaFuncSetAttribute(gemm_mma<4>, cudaFuncAttributeMaxDynamicSharedMemorySize, GEMM_SMEM);
    cudaFuncSetAttribute(flash_mma,   cudaFuncAttributeMaxDynamicSharedMemorySize, FLASH_SMEM);

    // 1. fused conversions (x 2-limb, weights 1-limb, ktmp row0)
    cvt_all<<<(CVT_TOTAL + 255) / 256, 256>>>(x, Wq, Wk, Wv, Wo, Wconv,
                                              xh, xl, wq, wkv, wo, wc, kth, ktl);

    // 2. fused conv-pooling GEMM (y<32) + Q projection (y>=32)
    gemm_convq<<<dim3(8, 128), GTHREADS, GEMM_SMEM>>>(xh, xl, wc, wq,
                                                      kth, ktl, qh, ql);

    // 3. fused K+V projection (N=2048) -> kh, vh (1-limb)
    gemm_mma<4><<<dim3(16, 33), GTHREADS, GEMM_SMEM>>>(kth, ktl, wkv,
        nullptr, kh, vh, nullptr, NB * TK, ND);

    // 4. HMMA masked flash attention -> o hi/lo
    flash_mma<<<dim3(NT / 128, NB * NH), 256, FLASH_SMEM>>>(qh, ql, kh, vh, oh, ol);

    // 5. output projection + bias -> d_out
    gemm_mma<2><<<dim3(8, 96), GTHREADS, GEMM_SMEM>>>(oh, ol, wo,
        out, nullptr, nullptr, bo, NB * NT, ND);
}

// round 15
// speedup vs baseline: 1.4959x; 1.0155x over previous
#include <cuda_runtime.h>
#include <cuda_fp16.h>
#include <cstdint>

#define NB 4
#define NT 3072
#define ND 1024
#define NH 16
#define HD 64
#define TK 1025   // pooled K/V length: 1 + 3072/3

// GEMM tiling: 128x128 CTA tile, BK=32 halfs, 8 warps (4M x 2N), warp tile 32x64
#define BM 128
#define BN 128
#define BKH 32
#define TILE_HALFS (128 * 40)
#define STAGE_HALFS (3 * TILE_HALFS)           // Ah, Al, Bh
#define NSTAGE 3
#define GEMM_SMEM (NSTAGE * STAGE_HALFS * 2)   // 92160 B
#define GTHREADS 256

// Q pre-scale: 1/sqrt(64) * log2(e)  (flash uses exp2)
#define QSCALE 0.1803368801111204f

// Flash tiling: 128 q x 64 keys, 8 warps (1 m16 each), stride 72 halfs (144B)
#define FS_STRIDE 144
#define FS_TILE_B (64 * FS_STRIDE)             // 9216 B (64x64 fp16 tile)
#define FS_STAGE_B (2 * FS_TILE_B)             // Kh + Vh = 18432
#define FLASH_SMEM (3 * FS_STAGE_B)            // 55296 B (3-stage; covers Q staging 36864)

// ---------------- scratch (device globals: no allocations allowed) ----------
__device__ __align__(256) __half g_xh[NB * NT * ND], g_xl[NB * NT * ND];
__device__ __align__(256) __half g_kth[NB * TK * ND], g_ktl[NB * TK * ND];  // pooled
__device__ __align__(256) __half g_oh[NB * NT * ND], g_ol[NB * NT * ND];    // attn out
__device__ __align__(256) __half g_qh[NB * NT * ND], g_ql[NB * NT * ND];
__device__ __align__(256) __half g_kh[NB * TK * ND];    // 1-limb K
__device__ __align__(256) __half g_vh[NB * TK * ND];    // 1-limb V
__device__ __align__(256) __half g_wq[ND * ND];
__device__ __align__(256) __half g_wkv[2 * ND * ND];    // Wk rows 0-1023, Wv 1024-2047
__device__ __align__(256) __half g_wo[ND * ND];
__device__ __align__(256) __half g_wc[ND * 3 * ND];     // Wconv transposed

// ---------------- PTX helpers ------------------------------------------------
__device__ __forceinline__ uint32_t smem_u32(const void* p) {
    uint32_t a;
    asm("{ .reg .u64 t; cvta.to.shared.u64 t, %1; cvt.u32.u64 %0, t; }" : "=r"(a) : "l"(p));
    return a;
}
__device__ __forceinline__ void cpa16(uint32_t dst, const void* src) {
    asm volatile("cp.async.cg.shared.global [%0], [%1], 16;" :: "r"(dst), "l"(src) : "memory");
}
__device__ __forceinline__ void ldsm4(uint32_t* r, uint32_t addr) {
    asm volatile("ldmatrix.sync.aligned.m8n8.x4.shared.b16 {%0,%1,%2,%3}, [%4];"
                 : "=r"(r[0]), "=r"(r[1]), "=r"(r[2]), "=r"(r[3]) : "r"(addr));
}
__device__ __forceinline__ void ldsm4t(uint32_t* r, uint32_t addr) {
    asm volatile("ldmatrix.sync.aligned.m8n8.x4.trans.shared.b16 {%0,%1,%2,%3}, [%4];"
                 : "=r"(r[0]), "=r"(r[1]), "=r"(r[2]), "=r"(r[3]) : "r"(addr));
}
__device__ __forceinline__ void mmah(float* d, const uint32_t* a, uint32_t b0, uint32_t b1) {
    asm volatile("mma.sync.aligned.m16n8k16.row.col.f32.f16.f16.f32 "
                 "{%0,%1,%2,%3}, {%4,%5,%6,%7}, {%8,%9}, {%0,%1,%2,%3};"
                 : "+f"(d[0]), "+f"(d[1]), "+f"(d[2]), "+f"(d[3])
                 : "r"(a[0]), "r"(a[1]), "r"(a[2]), "r"(a[3]), "r"(b0), "r"(b1));
}
__device__ __forceinline__ uint32_t packh(__half a, __half b) {
    __half2 t = __halves2half2(a, b);
    return *(uint32_t*)&t;
}
__device__ __forceinline__ float fexp2(float x) {
    float r;
    asm("ex2.approx.f32 %0, %1;" : "=f"(r) : "f"(x));
    return r;
}

// ---------------- fused conversion kernel ------------------------------------
// x (2-limb), Wq/Wk/Wv/Wo/Wconv-transpose (1-limb), ktmp row0 prepend (2-limb).
#define NW (ND * ND)
#define NX (NB * NT * ND)
#define CVT_TOTAL (NX + 7 * NW + NB * ND)
__global__ void cvt_all(const float* __restrict__ x,
                        const float* __restrict__ Wq, const float* __restrict__ Wk,
                        const float* __restrict__ Wv, const float* __restrict__ Wo,
                        const float* __restrict__ Wc,
                        __half* __restrict__ xh, __half* __restrict__ xl,
                        __half* __restrict__ wq, __half* __restrict__ wkv,
                        __half* __restrict__ wo, __half* __restrict__ wc,
                        __half* __restrict__ kth, __half* __restrict__ ktl) {
    int idx = blockIdx.x * 256 + threadIdx.x;
    float v;
    __half* ph;
    __half* pl = nullptr;
    if (idx < NX) {
        v = x[idx]; ph = xh + idx; pl = xl + idx;
    } else {
        int j = idx - NX;
        if (j < NW) {
            v = Wq[j]; ph = wq + j;
        } else if (j < 2 * NW) {
            int i = j - NW;
            v = Wk[i]; ph = wkv + i;
        } else if (j < 3 * NW) {
            int i = j - 2 * NW;
            v = Wv[i]; ph = wkv + NW + i;
        } else if (j < 4 * NW) {
            int i = j - 3 * NW;
            v = Wo[i]; ph = wo + i;
        } else if (j < 7 * NW) {
            int i = j - 4 * NW;
            int o = i / (3 * ND);
            int r = i - o * 3 * ND;
            int kw = r >> 10, ii = r & 1023;
            v = Wc[(size_t)o * 3 * ND + (size_t)ii * 3 + kw];
            ph = wc + i;
        } else if (j < 7 * NW + NB * ND) {
            int i = j - 7 * NW;
            int b = i >> 10, d = i & 1023;
            v = x[(size_t)b * NT * ND + d];
            ph = kth + (size_t)b * TK * ND + d;
            pl = ktl + (size_t)b * TK * ND + d;
        } else return;
    }
    __half hh = __float2half_rn(v);
    *ph = hh;
    if (pl) *pl = __float2half_rn(v - __half2float(hh));
}

// ---------------- fused conv + Q projection GEMM ------------------------------
// blockIdx.y < 32 -> conv pooling GEMM (M=4096, K=3072, strided x view, ktmp out)
// blockIdx.y >= 32 -> Q projection (out pre-scaled by QSCALE for exp2 flash)
__global__ void __launch_bounds__(GTHREADS, 1)
gemm_convq(const __half* __restrict__ xh, const __half* __restrict__ xl,
           const __half* __restrict__ wc, const __half* __restrict__ wq,
           __half* __restrict__ kth, __half* __restrict__ ktl,
           __half* __restrict__ qhd, __half* __restrict__ qld) {
    extern __shared__ __align__(128) __half sm[];
    uint32_t sb = smem_u32(sm);
    int tid = threadIdx.x;
    bool conv = blockIdx.y < 32;
    int bm = conv ? blockIdx.y * BM : (blockIdx.y - 32) * BM;
    int bn = blockIdx.x * BN;
    int K = conv ? 3 * ND : ND;
    int NKT = K >> 5;
    const __half* W = conv ? wc : wq;
    int lane = tid & 31, wid = tid >> 5;
    int wm = wid & 3, wn = wid >> 2;

    float acc[2][8][4];
#pragma unroll
    for (int i = 0; i < 2; i++)
#pragma unroll
        for (int j = 0; j < 8; j++)
#pragma unroll
            for (int v = 0; v < 4; v++) acc[i][j][v] = 0.f;

    auto load_stage = [&](int kt, int s) {
        int k0 = kt * BKH;
        uint32_t sbase = sb + (uint32_t)s * STAGE_HALFS * 2;
#pragma unroll
        for (int t = 0; t < 6; t++) {
            int q = tid + t * GTHREADS;
            int tile = q >> 9;                 // 0=Ah 1=Al 2=Bh
            int idx = q & 511;
            int r = idx >> 2, c = idx & 3;
            uint32_t dst = sbase + (uint32_t)tile * TILE_HALFS * 2 + r * 80 + c * 16;
            const __half* src;
            if (tile < 2) {
                int row = bm + r;
                size_t off;
                if (conv) off = ((size_t)(row >> 10) * NT + (size_t)(row & 1023) * 3) * ND;
                else      off = (size_t)row * ND;
                src = (tile ? xl : xh) + off + k0 + c * 8;
            } else {
                src = W + (size_t)(bn + r) * K + k0 + c * 8;
            }
            cpa16(dst, src);
        }
        asm volatile("cp.async.commit_group;" ::: "memory");
    };

    load_stage(0, 0);
    load_stage(1, 1);

    int s_cur = 0;
    for (int kt = 0; kt < NKT; kt++) {
        if (kt + 1 < NKT) { asm volatile("cp.async.wait_group 1;" ::: "memory"); }
        else              { asm volatile("cp.async.wait_group 0;" ::: "memory"); }
        __syncthreads();
        if (kt + 2 < NKT) {
            int s2 = s_cur + 2; if (s2 >= NSTAGE) s2 -= NSTAGE;
            load_stage(kt + 2, s2);
        }

        uint32_t st  = sb + (uint32_t)s_cur * STAGE_HALFS * 2;
        uint32_t aHi = st;
        uint32_t aLo = st + TILE_HALFS * 2;
        uint32_t bHi = st + 2 * TILE_HALFS * 2;

#pragma unroll
        for (int ks = 0; ks < 2; ks++) {
            uint32_t a_hi[2][4], a_lo[2][4];
            uint32_t aoff = (uint32_t)(wm * 32 + (lane & 15)) * 80 + ks * 32 + ((lane >> 4) << 4);
            ldsm4(a_hi[0], aHi + aoff);
            ldsm4(a_hi[1], aHi + aoff + 16 * 80);
            ldsm4(a_lo[0], aLo + aoff);
            ldsm4(a_lo[1], aLo + aoff + 16 * 80);

            uint32_t boff = (uint32_t)((lane & 7) + ((lane >> 4) << 3)) * 80
                          + (((lane >> 3) & 1) << 4) + ks * 32;
#pragma unroll
            for (int j = 0; j < 4; j++) {
                uint32_t b_hi[4];
                uint32_t bo = boff + (uint32_t)(wn * 64 + j * 16) * 80;
                ldsm4(b_hi, bHi + bo);
#pragma unroll
                for (int p = 0; p < 2; p++) {
                    int nj = j * 2 + p;
#pragma unroll
                    for (int mi = 0; mi < 2; mi++) {
                        mmah(acc[mi][nj], a_hi[mi], b_hi[p * 2], b_hi[p * 2 + 1]);
                        mmah(acc[mi][nj], a_lo[mi], b_hi[p * 2], b_hi[p * 2 + 1]);
                    }
                }
            }
        }
        if (++s_cur == NSTAGE) s_cur = 0;
    }

    __half* Ch = conv ? kth : qhd;
    __half* Cl = conv ? ktl : qld;
    float cs = conv ? 1.0f : QSCALE;
    int tq = lane >> 2, tr = lane & 3;
#pragma unroll
    for (int mi = 0; mi < 2; mi++) {
#pragma unroll
        for (int half = 0; half < 2; half++) {
            int row = bm + wm * 32 + mi * 16 + tq + half * 8;
            int orow = conv ? ((row >> 10) * TK + (row & 1023) + 1) : row;
#pragma unroll
            for (int nj = 0; nj < 8; nj++) {
                int col = bn + wn * 64 + nj * 8 + tr * 2;
                float v0 = acc[mi][nj][half * 2 + 0] * cs;
                float v1 = acc[mi][nj][half * 2 + 1] * cs;
                __half h0 = __float2half_rn(v0);
                __half h1 = __float2half_rn(v1);
                *(uint32_t*)(Ch + (size_t)orow * ND + col) = packh(h0, h1);
                *(uint32_t*)(Cl + (size_t)orow * ND + col) =
                    packh(__float2half_rn(v0 - __half2float(h0)),
                          __float2half_rn(v1 - __half2float(h1)));
            }
        }
    }
}

// ---------------- HMMA fp16x2 GEMM (KV and Wo) --------------------------------
// EPI 2: fp32+bias out. EPI 4: hi-only split cols<1024 -> Chi, >=1024 -> C2h.
template <int EPI>
__global__ void __launch_bounds__(GTHREADS, 1)
gemm_mma(const __half* __restrict__ Ahi, const __half* __restrict__ Alo,
         const __half* __restrict__ Whi,
         float* __restrict__ Cf, __half* __restrict__ Chi, __half* __restrict__ C2h,
         const float* __restrict__ bias, int M, int K) {
    extern __shared__ __align__(128) __half sm[];
    uint32_t sb = smem_u32(sm);
    int tid = threadIdx.x;
    int bm = blockIdx.y * BM, bn = blockIdx.x * BN;
    int NKT = K >> 5;
    int lane = tid & 31, wid = tid >> 5;
    int wm = wid & 3, wn = wid >> 2;

    float acc[2][8][4];
#pragma unroll
    for (int i = 0; i < 2; i++)
#pragma unroll
        for (int j = 0; j < 8; j++)
#pragma unroll
            for (int v = 0; v < 4; v++) acc[i][j][v] = 0.f;

    auto load_stage = [&](int kt, int s) {
        int k0 = kt * BKH;
        uint32_t sbase = sb + (uint32_t)s * STAGE_HALFS * 2;
#pragma unroll
        for (int t = 0; t < 6; t++) {
            int q = tid + t * GTHREADS;
            int tile = q >> 9;
            int idx = q & 511;
            int r = idx >> 2, c = idx & 3;
            uint32_t dst = sbase + (uint32_t)tile * TILE_HALFS * 2 + r * 80 + c * 16;
            const __half* src;
            if (tile < 2) {
                int row = bm + r;
                if (row > M - 1) row = M - 1;
                src = (tile ? Alo : Ahi) + (size_t)row * K + k0 + c * 8;
            } else {
                src = Whi + (size_t)(bn + r) * K + k0 + c * 8;
            }
            cpa16(dst, src);
        }
        asm volatile("cp.async.commit_group;" ::: "memory");
    };

    load_stage(0, 0);
    load_stage(1, 1);

    int s_cur = 0;
    for (int kt = 0; kt < NKT; kt++) {
        if (kt + 1 < NKT) { asm volatile("cp.async.wait_group 1;" ::: "memory"); }
        else              { asm volatile("cp.async.wait_group 0;" ::: "memory"); }
        __syncthreads();
        if (kt + 2 < NKT) {
            int s2 = s_cur + 2; if (s2 >= NSTAGE) s2 -= NSTAGE;
            load_stage(kt + 2, s2);
        }

        uint32_t st  = sb + (uint32_t)s_cur * STAGE_HALFS * 2;
        uint32_t aHi = st;
        uint32_t aLo = st + TILE_HALFS * 2;
        uint32_t bHi = st + 2 * TILE_HALFS * 2;

#pragma unroll
        for (int ks = 0; ks < 2; ks++) {
            uint32_t a_hi[2][4], a_lo[2][4];
            uint32_t aoff = (uint32_t)(wm * 32 + (lane & 15)) * 80 + ks * 32 + ((lane >> 4) << 4);
            ldsm4(a_hi[0], aHi + aoff);
            ldsm4(a_hi[1], aHi + aoff + 16 * 80);
            ldsm4(a_lo[0], aLo + aoff);
            ldsm4(a_lo[1], aLo + aoff + 16 * 80);

            uint32_t boff = (uint32_t)((lane & 7) + ((lane >> 4) << 3)) * 80
                          + (((lane >> 3) & 1) << 4) + ks * 32;
#pragma unroll
            for (int j = 0; j < 4; j++) {
                uint32_t b_hi[4];
                uint32_t bo = boff + (uint32_t)(wn * 64 + j * 16) * 80;
                ldsm4(b_hi, bHi + bo);
#pragma unroll
                for (int p = 0; p < 2; p++) {
                    int nj = j * 2 + p;
#pragma unroll
                    for (int mi = 0; mi < 2; mi++) {
                        mmah(acc[mi][nj], a_hi[mi], b_hi[p * 2], b_hi[p * 2 + 1]);
                        mmah(acc[mi][nj], a_lo[mi], b_hi[p * 2], b_hi[p * 2 + 1]);
                    }
                }
            }
        }
        if (++s_cur == NSTAGE) s_cur = 0;
    }

    int tq = lane >> 2, tr = lane & 3;
#pragma unroll
    for (int mi = 0; mi < 2; mi++) {
#pragma unroll
        for (int half = 0; half < 2; half++) {
            int row = bm + wm * 32 + mi * 16 + tq + half * 8;
            if (row >= M) continue;
#pragma unroll
            for (int nj = 0; nj < 8; nj++) {
                int col = bn + wn * 64 + nj * 8 + tr * 2;
                float v0 = acc[mi][nj][half * 2 + 0];
                float v1 = acc[mi][nj][half * 2 + 1];
                if (EPI == 4) {
                    __half* ph = (col < ND) ? (Chi + (size_t)row * ND + col)
                                            : (C2h + (size_t)row * ND + (col - ND));
                    *(uint32_t*)ph = packh(__float2half_rn(v0), __float2half_rn(v1));
                } else {
                    v0 += bias[col]; v1 += bias[col + 1];
                    float2 f2; f2.x = v0; f2.y = v1;
                    *(float2*)(Cf + (size_t)row * ND + col) = f2;
                }
            }
        }
    }
}

// ---------------- HMMA flash attention (fp16x2, exp2 domain) ------------------
// Q pre-scaled by QSCALE; scores are log2-domain. 3-stage KV ring, 1 sync/tile.
__global__ void __launch_bounds__(256, 1)
flash_mma(const __half* __restrict__ Qh, const __half* __restrict__ Ql,
          const __half* __restrict__ Kh, const __half* __restrict__ Vh,
          __half* __restrict__ Oh, __half* __restrict__ Ol) {
    extern __shared__ __align__(128) char fsm[];
    uint32_t sb = smem_u32(fsm);
    int tid = threadIdx.x, lane = tid & 31, w = tid >> 5;
    int bh = blockIdx.y;
    int b = bh >> 4, h = bh & 15;
    int q0 = blockIdx.x * 128;

    const __half* qhg = Qh + ((size_t)b * NT + q0) * ND + h * HD;
    const __half* qlg = Ql + ((size_t)b * NT + q0) * ND + h * HD;
    const __half* khg = Kh + (size_t)b * TK * ND + h * HD;
    const __half* vhg = Vh + (size_t)b * TK * ND + h * HD;

    // ---- stage Q (128x64 hi/lo), extract A fragments ------------------------
#pragma unroll
    for (int t = 0; t < 8; t++) {
        int idx = tid + (t & 3) * 256;
        int r = idx >> 3, c = idx & 7;
        const __half* g = (t < 4) ? qhg : qlg;
        cpa16(sb + (t < 4 ? 0 : 18432) + r * FS_STRIDE + c * 16,
              g + (size_t)r * ND + c * 8);
    }
    asm volatile("cp.async.commit_group;" ::: "memory");
    asm volatile("cp.async.wait_group 0;" ::: "memory");
    __syncthreads();

    uint32_t qfh[4][4], qfl[4][4];
    {
        uint32_t aoff = (uint32_t)(w * 16 + (lane & 15)) * FS_STRIDE + ((lane >> 4) << 4);
#pragma unroll
        for (int kc = 0; kc < 4; kc++) {
            ldsm4(qfh[kc], sb + aoff + kc * 32);
            ldsm4(qfl[kc], sb + 18432 + aoff + kc * 32);
        }
    }
    __syncthreads();

    float m0 = -1e30f, m1 = -1e30f, l0 = 0.f, l1 = 0.f;  // l: per-thread partial
    float ao[8][4];
#pragma unroll
    for (int j = 0; j < 8; j++)
#pragma unroll
        for (int v = 0; v < 4; v++) ao[j][v] = 0.f;

    int kmax_blk = (q0 + 127) / 3;
    int ntiles = kmax_blk / 64 + 1;
    int qwmax = q0 + w * 16 + 15;
    int qwmin = q0 + w * 16;
    int g8 = lane >> 2, tr2 = (lane & 3) * 2;
    int qa = qwmin + g8, qb = qa + 8;

    auto load_kv = [&](int kt, int s) {
        uint32_t bse = sb + (uint32_t)s * FS_STAGE_B;
        size_t koff = (size_t)kt * 64 * ND;
#pragma unroll
        for (int t = 0; t < 4; t++) {
            int idx = tid + (t & 1) * 256;
            int r = idx >> 3, c = idx & 7;
            const __half* g = (t < 2) ? khg : vhg;
            cpa16(bse + (uint32_t)(t >> 1) * FS_TILE_B + r * FS_STRIDE + c * 16,
                  g + koff + (size_t)r * ND + c * 8);
        }
        asm volatile("cp.async.commit_group;" ::: "memory");
    };

    load_kv(0, 0);
    if (ntiles > 1) load_kv(1, 1);

    int s_cur = 0;
    for (int kt = 0; kt < ntiles; kt++) {
        if (kt + 1 < ntiles) { asm volatile("cp.async.wait_group 1;" ::: "memory"); }
        else                 { asm volatile("cp.async.wait_group 0;" ::: "memory"); }
        __syncthreads();
        if (kt + 2 < ntiles) {
            int s2 = s_cur + 2; if (s2 >= 3) s2 -= 3;
            load_kv(kt + 2, s2);
        }
        int kt0 = kt * 64;
        if (3 * kt0 <= qwmax) {
            uint32_t st = sb + (uint32_t)s_cur * FS_STAGE_B;

            // ---- S = Q K^T (fp16x2, log2 domain) ---------------------------
            float sacc[8][4];
#pragma unroll
            for (int j = 0; j < 8; j++)
#pragma unroll
                for (int v = 0; v < 4; v++) sacc[j][v] = 0.f;

#pragma unroll
            for (int njp = 0; njp < 4; njp++) {
#pragma unroll
                for (int kc = 0; kc < 4; kc++) {
                    uint32_t boff = (uint32_t)(njp * 16 + (lane & 7) + ((lane >> 4) << 3)) * FS_STRIDE
                                  + kc * 32 + (((lane >> 3) & 1) << 4);
                    uint32_t bkh[4];
                    ldsm4(bkh, st + boff);
#pragma unroll
                    for (int p = 0; p < 2; p++) {
                        mmah(sacc[njp * 2 + p], qfh[kc], bkh[p * 2], bkh[p * 2 + 1]);
                        mmah(sacc[njp * 2 + p], qfl[kc], bkh[p * 2], bkh[p * 2 + 1]);
                    }
                }
            }

            // ---- mask (only boundary tiles) + row max ----------------------
            float rm0 = -1e30f, rm1 = -1e30f;
            bool need_mask = 3 * (kt0 + 63) > qwmin;
            if (need_mask) {
#pragma unroll
                for (int nj = 0; nj < 8; nj++) {
                    int key = kt0 + nj * 8 + tr2;
                    float s0 = sacc[nj][0]; if (3 * key > qa) s0 = -1e30f;
                    float s1 = sacc[nj][1]; if (3 * (key + 1) > qa) s1 = -1e30f;
                    float s2 = sacc[nj][2]; if (3 * key > qb) s2 = -1e30f;
                    float s3 = sacc[nj][3]; if (3 * (key + 1) > qb) s3 = -1e30f;
                    sacc[nj][0] = s0; sacc[nj][1] = s1; sacc[nj][2] = s2; sacc[nj][3] = s3;
                    rm0 = fmaxf(rm0, fmaxf(s0, s1));
                    rm1 = fmaxf(rm1, fmaxf(s2, s3));
                }
            } else {
#pragma unroll
                for (int nj = 0; nj < 8; nj++) {
                    rm0 = fmaxf(rm0, fmaxf(sacc[nj][0], sacc[nj][1]));
                    rm1 = fmaxf(rm1, fmaxf(sacc[nj][2], sacc[nj][3]));
                }
            }
            rm0 = fmaxf(rm0, __shfl_xor_sync(0xffffffffu, rm0, 1));
            rm0 = fmaxf(rm0, __shfl_xor_sync(0xffffffffu, rm0, 2));
            rm1 = fmaxf(rm1, __shfl_xor_sync(0xffffffffu, rm1, 1));
            rm1 = fmaxf(rm1, __shfl_xor_sync(0xffffffffu, rm1, 2));
            float nm0 = fmaxf(m0, rm0), nm1 = fmaxf(m1, rm1);
            float c0 = fexp2(m0 - nm0), c1 = fexp2(m1 - nm1);
            m0 = nm0; m1 = nm1;

            float ls0 = 0.f, ls1 = 0.f;
#pragma unroll
            for (int nj = 0; nj < 8; nj++) {
                float p0 = fexp2(sacc[nj][0] - m0);
                float p1 = fexp2(sacc[nj][1] - m0);
                float p2 = fexp2(sacc[nj][2] - m1);
                float p3 = fexp2(sacc[nj][3] - m1);
                sacc[nj][0] = p0; sacc[nj][1] = p1; sacc[nj][2] = p2; sacc[nj][3] = p3;
                ls0 += p0 + p1; ls1 += p2 + p3;
            }
            l0 = l0 * c0 + ls0;        // per-thread partial; reduced after loop
            l1 = l1 * c1 + ls1;
#pragma unroll
            for (int nj = 0; nj < 8; nj++) {
                ao[nj][0] *= c0; ao[nj][1] *= c0;
                ao[nj][2] *= c1; ao[nj][3] *= c1;
            }

            // ---- P -> fp16 hi/lo A fragments -------------------------------
            uint32_t pah[4][4], pal[4][4];
#pragma unroll
            for (int kc = 0; kc < 4; kc++) {
#pragma unroll
                for (int rr = 0; rr < 4; rr++) {
                    int nj = kc * 2 + (rr >> 1);
                    int vb = (rr & 1) * 2;
                    float pa = sacc[nj][vb], pb = sacc[nj][vb + 1];
                    __half ha = __float2half_rn(pa);
                    __half hb = __float2half_rn(pb);
                    pah[kc][rr] = packh(ha, hb);
                    pal[kc][rr] = packh(__float2half_rn(pa - __half2float(ha)),
                                        __float2half_rn(pb - __half2float(hb)));
                }
            }

            // ---- O += P V (fp16x2) -----------------------------------------
            uint32_t vbh = st + FS_TILE_B;
#pragma unroll
            for (int njp = 0; njp < 4; njp++) {
#pragma unroll
                for (int kc = 0; kc < 4; kc++) {
                    uint32_t voff = (uint32_t)(kc * 16 + (lane & 7) + (((lane >> 3) & 1) << 3)) * FS_STRIDE
                                  + (njp * 16 + (((lane >> 4) & 1) << 3)) * 2;
                    uint32_t bv[4];
                    ldsm4t(bv, vbh + voff);
#pragma unroll
                    for (int p = 0; p < 2; p++) {
                        mmah(ao[njp * 2 + p], pah[kc], bv[p * 2], bv[p * 2 + 1]);
                        mmah(ao[njp * 2 + p], pal[kc], bv[p * 2], bv[p * 2 + 1]);
                    }
                }
            }
        }
        if (++s_cur == 3) s_cur = 0;
    }

    // ---- final l reduction (deferred from the loop) --------------------------
    l0 += __shfl_xor_sync(0xffffffffu, l0, 1);
    l0 += __shfl_xor_sync(0xffffffffu, l0, 2);
    l1 += __shfl_xor_sync(0xffffffffu, l1, 1);
    l1 += __shfl_xor_sync(0xffffffffu, l1, 2);

    // ---- write O hi/lo ------------------------------------------------------
    float i0 = 1.f / l0, i1 = 1.f / l1;
    size_t rowa = ((size_t)b * NT + qa) * ND + h * HD;
    size_t rowb = rowa + (size_t)8 * ND;
#pragma unroll
    for (int nj = 0; nj < 8; nj++) {
        int col = nj * 8 + tr2;
        float v0 = ao[nj][0] * i0, v1 = ao[nj][1] * i0;
        float v2 = ao[nj][2] * i1, v3 = ao[nj][3] * i1;
        __half h0 = __float2half_rn(v0), h1 = __float2half_rn(v1);
        __half h2 = __float2half_rn(v2), h3 = __float2half_rn(v3);
        *(uint32_t*)(Oh + rowa + col) = packh(h0, h1);
        *(uint32_t*)(Ol + rowa + col) = packh(__float2half_rn(v0 - __half2float(h0)),
                                              __float2half_rn(v1 - __half2float(h1)));
        *(uint32_t*)(Oh + rowb + col) = packh(h2, h3);
        *(uint32_t*)(Ol + rowb + col) = packh(__float2half_rn(v2 - __half2float(h2)),
                                              __float2half_rn(v3 - __half2float(h3)));
    }
}

// ---------------- launch ------------------------------------------------------
extern "C" void kernel_launch(void* const* d_in, const int* in_sizes, int n_in,
                              void* d_out, int out_size) {
    const float* x     = (const float*)d_in[0];
    const float* Wq    = (const float*)d_in[1];
    const float* Wk    = (const float*)d_in[2];
    const float* Wv    = (const float*)d_in[3];
    const float* Wo    = (const float*)d_in[4];
    const float* bo    = (const float*)d_in[5];
    const float* Wconv = (const float*)d_in[6];
    float* out = (float*)d_out;

    __half *xh, *xl, *kth, *ktl, *oh, *ol, *qh, *ql, *kh, *vh;
    __half *wq, *wkv, *wo, *wc;
    cudaGetSymbolAddress((void**)&xh, g_xh);   cudaGetSymbolAddress((void**)&xl, g_xl);
    cudaGetSymbolAddress((void**)&kth, g_kth); cudaGetSymbolAddress((void**)&ktl, g_ktl);
    cudaGetSymbolAddress((void**)&oh, g_oh);   cudaGetSymbolAddress((void**)&ol, g_ol);
    cudaGetSymbolAddress((void**)&qh, g_qh);   cudaGetSymbolAddress((void**)&ql, g_ql);
    cudaGetSymbolAddress((void**)&kh, g_kh);   cudaGetSymbolAddress((void**)&vh, g_vh);
    cudaGetSymbolAddress((void**)&wq, g_wq);   cudaGetSymbolAddress((void**)&wkv, g_wkv);
    cudaGetSymbolAddress((void**)&wo, g_wo);   cudaGetSymbolAddress((void**)&wc, g_wc);

    cudaFuncSetAttribute(gemm_convq,  cudaFuncAttributeMaxDynamicSharedMemorySize, GEMM_SMEM);
    cudaFuncSetAttribute(gemm_mma<2>, cudaFuncAttributeMaxDynamicSharedMemorySize, GEMM_SMEM);
    cudaFuncSetAttribute(gemm_mma<4>, cudaFuncAttributeMaxDynamicSharedMemorySize, GEMM_SMEM);
    cudaFuncSetAttribute(flash_mma,   cudaFuncAttributeMaxDynamicSharedMemorySize, FLASH_SMEM);

    // 1. fused conversions (x 2-limb, weights 1-limb, ktmp row0)
    cvt_all<<<(CVT_TOTAL + 255) / 256, 256>>>(x, Wq, Wk, Wv, Wo, Wconv,
                                              xh, xl, wq, wkv, wo, wc, kth, ktl);

    // 2. fused conv-pooling GEMM (y<32) + Q projection (y>=32, pre-scaled)
    gemm_convq<<<dim3(8, 128), GTHREADS, GEMM_SMEM>>>(xh, xl, wc, wq,
                                                      kth, ktl, qh, ql);

    // 3. fused K+V projection (N=2048) -> kh, vh (1-limb)
    gemm_mma<4><<<dim3(16, 33), GTHREADS, GEMM_SMEM>>>(kth, ktl, wkv,
        nullptr, kh, vh, nullptr, NB * TK, ND);

    // 4. HMMA masked flash attention (exp2 domain) -> o hi/lo
    flash_mma<<<dim3(NT / 128, NB * NH), 256, FLASH_SMEM>>>(qh, ql, kh, vh, oh, ol);

    // 5. output projection + bias -> d_out
    gemm_mma<2><<<dim3(8, 96), GTHREADS, GEMM_SMEM>>>(oh, ol, wo,
        out, nullptr, nullptr, bo, NB * NT, ND);
}